// round 9
// baseline (speedup 1.0000x reference)
#include <cuda_runtime.h>
#include <cuda_bf16.h>
#include <cuda_fp16.h>
#include <cstdint>

#define NN 50000
#define EMAX 800000
#define EPS 1e-5f
#define HALF0 25088   // 196 * 128

// ======================= split bf16 pack/unpack =======================
__device__ __forceinline__ uint32_t pack_bf(float v) {
    __nv_bfloat16 h = __float2bfloat16(v);
    float hf = __bfloat162float(h);
    __nv_bfloat16 l = __float2bfloat16(v - hf);
    return ((uint32_t)__bfloat16_as_ushort(h) << 16) | (uint32_t)__bfloat16_as_ushort(l);
}

__device__ __forceinline__ void cpasync16(uint32_t dst, const void* src) {
    asm volatile("cp.async.cg.shared.global [%0], [%1], 16;" :: "r"(dst), "l"(src));
}
__device__ __forceinline__ void cpcommit() { asm volatile("cp.async.commit_group;" ::: "memory"); }
__device__ __forceinline__ void cpwait0()  { asm volatile("cp.async.wait_group 0;" ::: "memory"); }

// ======================= scratch =======================
__device__ uint32_t g_X[NN * 128];      // packed split-bf16 (GEMM input)
__device__ __half   g_Xh[NN * 128];     // fp16 gather table
__device__ uint32_t g_h1[NN * 256];
__device__ __half   g_h1h[NN * 256];
__device__ uint32_t g_h2[NN * 256];
__device__ __half   g_h2h[NN * 256];
__device__ uint32_t g_M[NN * 256];      // mean, packed split-bf16
__device__ float    g_P[NN * 256];
__device__ __align__(16) __nv_bfloat16 g_Bh[2 * 256 * 128 + 2 * 2 * 256 * 256];
__device__ __align__(16) __nv_bfloat16 g_Bl[2 * 256 * 128 + 2 * 2 * 256 * 256];
__device__ int g_counts[NN];
__device__ int g_offsets[NN + 1];
__device__ int g_cursor[NN];
__device__ int g_esrc[EMAX];
__device__ int g_bsum[256];
__device__ int g_boff[256];

// ======================= CSR build =======================
__global__ void zero_counts_kernel() {
    int i = blockIdx.x * blockDim.x + threadIdx.x;
    if (i < NN) g_counts[i] = 0;
}
__global__ void hist_kernel(const int* __restrict__ dst, int E) {
    int e = blockIdx.x * blockDim.x + threadIdx.x;
    if (e < E) atomicAdd(&g_counts[dst[e]], 1);
}
__global__ void block_sums_kernel() {
    __shared__ int s[256];
    int i = blockIdx.x * 256 + threadIdx.x;
    s[threadIdx.x] = (i < NN) ? g_counts[i] : 0;
    __syncthreads();
    #pragma unroll
    for (int off = 128; off > 0; off >>= 1) {
        if (threadIdx.x < off) s[threadIdx.x] += s[threadIdx.x + off];
        __syncthreads();
    }
    if (threadIdx.x == 0) g_bsum[blockIdx.x] = s[0];
}
__global__ void scan_bsums_kernel(int nb) {
    __shared__ int s[256];
    int v = (threadIdx.x < nb) ? g_bsum[threadIdx.x] : 0;
    s[threadIdx.x] = v;
    __syncthreads();
    #pragma unroll
    for (int off = 1; off < 256; off <<= 1) {
        int t = (threadIdx.x >= off) ? s[threadIdx.x - off] : 0;
        __syncthreads();
        s[threadIdx.x] += t;
        __syncthreads();
    }
    if (threadIdx.x < nb) g_boff[threadIdx.x] = s[threadIdx.x] - v;
    if (threadIdx.x == 255) g_offsets[NN] = s[255];
}
__global__ void scan_final_kernel() {
    __shared__ int s[256];
    int i = blockIdx.x * 256 + threadIdx.x;
    int v = (i < NN) ? g_counts[i] : 0;
    s[threadIdx.x] = v;
    __syncthreads();
    #pragma unroll
    for (int off = 1; off < 256; off <<= 1) {
        int t = (threadIdx.x >= off) ? s[threadIdx.x - off] : 0;
        __syncthreads();
        s[threadIdx.x] += t;
        __syncthreads();
    }
    if (i < NN) {
        g_offsets[i] = g_boff[blockIdx.x] + s[threadIdx.x] - v;
        g_cursor[i] = 0;
    }
}
__global__ void scatter_kernel(const int* __restrict__ src, const int* __restrict__ dst, int E) {
    int e = blockIdx.x * blockDim.x + threadIdx.x;
    if (e < E) {
        int d = dst[e];
        int p = atomicAdd(&g_cursor[d], 1);
        g_esrc[g_offsets[d] + p] = src[e];
    }
}

// ======================= conversion =======================
__global__ void conv_x_kernel(const float* __restrict__ x) {
    int i = blockIdx.x * blockDim.x + threadIdx.x;
    if (i < NN * 128) {
        float v = x[i];
        g_X[i] = pack_bf(v);
        g_Xh[i] = __float2half(v);
    }
}
__global__ void conv_w_kernel(const float* __restrict__ Wl, const float* __restrict__ Wr,
                              __nv_bfloat16* __restrict__ Bh, __nv_bfloat16* __restrict__ Bl,
                              int K) {
    int i = blockIdx.x * blockDim.x + threadIdx.x;
    int tot = 2 * 256 * K;
    if (i >= tot) return;
    int mat = i / (256 * K);
    int r = i - mat * 256 * K;
    int n = r / K;
    int k = r - n * K;
    const float* W = mat ? Wr : Wl;
    float f = W[k * 256 + n];
    __nv_bfloat16 h = __float2bfloat16(f);
    __nv_bfloat16 l = __float2bfloat16(f - __bfloat162float(h));
    Bh[i] = h;
    Bl[i] = l;
}

// ======================= mean aggregation (fp16 gather) =======================
// One warp per 128-feature half; lane handles 4 features via uint2 (4 halves).
template <int NHALF>
__global__ __launch_bounds__(256) void agg_f16(const __half* __restrict__ h,
                                               uint32_t* __restrict__ mean,
                                               int nodeBeg, int nodeEnd) {
    int gw = (blockIdx.x * blockDim.x + threadIdx.x) >> 5;
    int nNodes = nodeEnd - nodeBeg;
    if (gw >= nNodes * NHALF) return;
    int node, half;
    if (NHALF == 2) { node = nodeBeg + (gw >> 1); half = gw & 1; }
    else            { node = nodeBeg + gw;        half = 0; }
    int lane = threadIdx.x & 31;
    int beg = g_offsets[node], end = g_offsets[node + 1];

    const int RS = NHALF * 32;   // row stride in uint2 (4-half) units
    const uint2* base = reinterpret_cast<const uint2*>(h) + half * 32 + lane;

    float a0 = 0.f, a1 = 0.f, a2 = 0.f, a3 = 0.f;
    int e = beg;
    for (; e + 4 <= end; e += 4) {
        int s0 = g_esrc[e + 0];
        int s1 = g_esrc[e + 1];
        int s2 = g_esrc[e + 2];
        int s3 = g_esrc[e + 3];
        uint2 t0 = __ldg(base + (size_t)s0 * RS);
        uint2 t1 = __ldg(base + (size_t)s1 * RS);
        uint2 t2 = __ldg(base + (size_t)s2 * RS);
        uint2 t3 = __ldg(base + (size_t)s3 * RS);
        float2 f0a = __half22float2(*(const __half2*)&t0.x), f0b = __half22float2(*(const __half2*)&t0.y);
        float2 f1a = __half22float2(*(const __half2*)&t1.x), f1b = __half22float2(*(const __half2*)&t1.y);
        float2 f2a = __half22float2(*(const __half2*)&t2.x), f2b = __half22float2(*(const __half2*)&t2.y);
        float2 f3a = __half22float2(*(const __half2*)&t3.x), f3b = __half22float2(*(const __half2*)&t3.y);
        a0 += f0a.x + f1a.x + f2a.x + f3a.x;
        a1 += f0a.y + f1a.y + f2a.y + f3a.y;
        a2 += f0b.x + f1b.x + f2b.x + f3b.x;
        a3 += f0b.y + f1b.y + f2b.y + f3b.y;
    }
    for (; e < end; e++) {
        int s = g_esrc[e];
        uint2 t = __ldg(base + (size_t)s * RS);
        float2 fa = __half22float2(*(const __half2*)&t.x);
        float2 fb = __half22float2(*(const __half2*)&t.y);
        a0 += fa.x; a1 += fa.y; a2 += fb.x; a3 += fb.y;
    }

    int deg = end - beg;
    float inv = 1.0f / (float)(deg > 1 ? deg : 1);
    uint4 o;
    o.x = pack_bf(a0 * inv);
    o.y = pack_bf(a1 * inv);
    o.z = pack_bf(a2 * inv);
    o.w = pack_bf(a3 * inv);
    // packed mean row: NHALF*32 uint4 per node; same feature mapping as gather
    reinterpret_cast<uint4*>(mean)[(size_t)node * RS + half * 32 + lane] = o;
}

// ======================= mma.sync helper =======================
__device__ __forceinline__ void mma16816(float* c, const uint32_t* a, uint32_t b0, uint32_t b1) {
    asm("mma.sync.aligned.m16n8k16.row.col.f32.bf16.bf16.f32 "
        "{%0,%1,%2,%3}, {%4,%5,%6,%7}, {%8,%9}, {%0,%1,%2,%3};"
        : "+f"(c[0]), "+f"(c[1]), "+f"(c[2]), "+f"(c[3])
        : "r"(a[0]), "r"(a[1]), "r"(a[2]), "r"(a[3]), "r"(b0), "r"(b1));
}

// ======================= double-buffered single-matrix GEMM =======================
#define SST 40
#define PLANE_B (128 * SST * 2)
#define BUF_B   (4 * PLANE_B)
#define GSMEM   (2 * BUF_B)

template <int K, bool SELF, bool PACK_OUT, bool RELU>
__global__ __launch_bounds__(256, 2) void gemm_one(
    const uint32_t* __restrict__ A,
    const __nv_bfloat16* __restrict__ Bh, const __nv_bfloat16* __restrict__ Bl,
    const float* __restrict__ P,
    const float* __restrict__ blv, const float* __restrict__ gam,
    const float* __restrict__ bet, const float* __restrict__ rm,
    const float* __restrict__ rv,
    void* __restrict__ outv, __half* __restrict__ outh, int rowOff, int M)
{
    extern __shared__ __align__(16) char dsm[];
    constexpr int NC = K / 32;

    int tid = threadIdx.x;
    int lane = tid & 31;
    int wid = tid >> 5;
    int g = lane >> 2;
    int tig = lane & 3;
    int wm = wid & 3;
    int wn = wid >> 2;
    int mBase = rowOff + blockIdx.x * 128;
    int nBase = blockIdx.y * 128;

    float acc[2][8][4];
    #pragma unroll
    for (int mt = 0; mt < 2; mt++)
        #pragma unroll
        for (int nt = 0; nt < 8; nt++)
            #pragma unroll
            for (int q = 0; q < 4; q++) acc[mt][nt][q] = 0.f;

    auto stageB = [&](int kc, int buf) {
        char* base = dsm + buf * BUF_B;
        uint32_t dBh = (uint32_t)__cvta_generic_to_shared(base + 2 * PLANE_B);
        uint32_t dBl = (uint32_t)__cvta_generic_to_shared(base + 3 * PLANE_B);
        #pragma unroll
        for (int i = 0; i < 2; i++) {
            int lin = tid + i * 256;
            int row = lin >> 2;
            int c8 = lin & 3;
            uint32_t doff = (uint32_t)(row * (SST * 2) + c8 * 16);
            const __nv_bfloat16* sh = Bh + (size_t)(nBase + row) * K + kc * 32 + c8 * 8;
            const __nv_bfloat16* sl = Bl + (size_t)(nBase + row) * K + kc * 32 + c8 * 8;
            cpasync16(dBh + doff, sh);
            cpasync16(dBl + doff, sl);
        }
        cpcommit();
    };
    auto loadA = [&](int kc, uint2* pa) {
        #pragma unroll
        for (int i = 0; i < 8; i++) {
            int lin = tid + i * 256;
            int row = lin >> 4;
            int c2 = lin & 15;
            int grow = mBase + row;
            pa[i] = (grow < M) ? ((const uint2*)(A + (size_t)grow * K + kc * 32))[c2]
                               : make_uint2(0u, 0u);
        }
    };
    auto storeA = [&](int buf, const uint2* pa) {
        char* base = dsm + buf * BUF_B;
        __nv_bfloat16* sAh = (__nv_bfloat16*)(base);
        __nv_bfloat16* sAl = (__nv_bfloat16*)(base + PLANE_B);
        #pragma unroll
        for (int i = 0; i < 8; i++) {
            int lin = tid + i * 256;
            int row = lin >> 4;
            int c2 = lin & 15;
            uint32_t hu = (pa[i].x >> 16) | (pa[i].y & 0xffff0000u);
            uint32_t lu = (pa[i].x & 0xffffu) | (pa[i].y << 16);
            *(uint32_t*)&sAh[row * SST + c2 * 2] = hu;
            *(uint32_t*)&sAl[row * SST + c2 * 2] = lu;
        }
    };

    uint2 pa[8];
    stageB(0, 0);
    loadA(0, pa);
    storeA(0, pa);
    cpwait0();
    __syncthreads();

    for (int kc = 0; kc < NC; kc++) {
        int cur = kc & 1;
        int nxt = cur ^ 1;
        bool more = (kc + 1 < NC);
        if (more) {
            stageB(kc + 1, nxt);
            loadA(kc + 1, pa);
        }
        {
            char* base = dsm + cur * BUF_B;
            const __nv_bfloat16* sAh = (const __nv_bfloat16*)(base);
            const __nv_bfloat16* sAl = (const __nv_bfloat16*)(base + PLANE_B);
            const __nv_bfloat16* sBh = (const __nv_bfloat16*)(base + 2 * PLANE_B);
            const __nv_bfloat16* sBl = (const __nv_bfloat16*)(base + 3 * PLANE_B);
            #pragma unroll
            for (int ks = 0; ks < 2; ks++) {
                int k0 = ks * 16;
                uint32_t ah[2][4], al[2][4];
                #pragma unroll
                for (int mt = 0; mt < 2; mt++) {
                    int r0 = (wm * 32 + mt * 16 + g) * SST + k0 + 2 * tig;
                    ah[mt][0] = *(const uint32_t*)&sAh[r0];
                    ah[mt][1] = *(const uint32_t*)&sAh[r0 + 8 * SST];
                    ah[mt][2] = *(const uint32_t*)&sAh[r0 + 8];
                    ah[mt][3] = *(const uint32_t*)&sAh[r0 + 8 * SST + 8];
                    al[mt][0] = *(const uint32_t*)&sAl[r0];
                    al[mt][1] = *(const uint32_t*)&sAl[r0 + 8 * SST];
                    al[mt][2] = *(const uint32_t*)&sAl[r0 + 8];
                    al[mt][3] = *(const uint32_t*)&sAl[r0 + 8 * SST + 8];
                }
                #pragma unroll
                for (int nt = 0; nt < 8; nt++) {
                    int b0 = (wn * 64 + nt * 8 + g) * SST + k0 + 2 * tig;
                    uint32_t bh0 = *(const uint32_t*)&sBh[b0];
                    uint32_t bh1 = *(const uint32_t*)&sBh[b0 + 8];
                    uint32_t bl0 = *(const uint32_t*)&sBl[b0];
                    uint32_t bl1 = *(const uint32_t*)&sBl[b0 + 8];
                    #pragma unroll
                    for (int mt = 0; mt < 2; mt++) {
                        mma16816(acc[mt][nt], ah[mt], bh0, bh1);
                        mma16816(acc[mt][nt], al[mt], bh0, bh1);
                        mma16816(acc[mt][nt], ah[mt], bl0, bl1);
                    }
                }
            }
        }
        if (more) {
            storeA(nxt, pa);
            cpwait0();
        }
        __syncthreads();
    }

    if (SELF) {
        float* out = (float*)outv;
        #pragma unroll
        for (int nt = 0; nt < 8; nt++) {
            int c0 = nBase + wn * 64 + nt * 8 + 2 * tig;
            #pragma unroll
            for (int mt = 0; mt < 2; mt++) {
                int r0 = mBase + wm * 32 + mt * 16 + g;
                int r1 = r0 + 8;
                if (r0 < M)
                    *(float2*)(out + (size_t)r0 * 256 + c0) = make_float2(acc[mt][nt][0], acc[mt][nt][1]);
                if (r1 < M)
                    *(float2*)(out + (size_t)r1 * 256 + c0) = make_float2(acc[mt][nt][2], acc[mt][nt][3]);
            }
        }
    } else {
        uint32_t* out = (uint32_t*)outv;
        #pragma unroll
        for (int nt = 0; nt < 8; nt++) {
            int c0 = nBase + wn * 64 + nt * 8 + 2 * tig;
            int c1 = c0 + 1;
            float sc0 = gam[c0] * rsqrtf(rv[c0] + EPS);
            float sh0 = (blv[c0] - rm[c0]) * sc0 + bet[c0];
            float sc1 = gam[c1] * rsqrtf(rv[c1] + EPS);
            float sh1 = (blv[c1] - rm[c1]) * sc1 + bet[c1];
            #pragma unroll
            for (int mt = 0; mt < 2; mt++) {
                int r0 = mBase + wm * 32 + mt * 16 + g;
                int r1 = r0 + 8;
                if (r0 < M) {
                    float2 p = *(const float2*)(P + (size_t)r0 * 256 + c0);
                    float v00 = (acc[mt][nt][0] + p.x) * sc0 + sh0;
                    float v01 = (acc[mt][nt][1] + p.y) * sc1 + sh1;
                    if (RELU) { v00 = fmaxf(v00, 0.f); v01 = fmaxf(v01, 0.f); }
                    uint2 w;
                    w.x = PACK_OUT ? pack_bf(v00) : __float_as_uint(v00);
                    w.y = PACK_OUT ? pack_bf(v01) : __float_as_uint(v01);
                    *(uint2*)(out + (size_t)r0 * 256 + c0) = w;
                    if (PACK_OUT) {
                        __half2 hv = __floats2half2_rn(v00, v01);
                        *(__half2*)(outh + (size_t)r0 * 256 + c0) = hv;
                    }
                }
                if (r1 < M) {
                    float2 p = *(const float2*)(P + (size_t)r1 * 256 + c0);
                    float v10 = (acc[mt][nt][2] + p.x) * sc0 + sh0;
                    float v11 = (acc[mt][nt][3] + p.y) * sc1 + sh1;
                    if (RELU) { v10 = fmaxf(v10, 0.f); v11 = fmaxf(v11, 0.f); }
                    uint2 w;
                    w.x = PACK_OUT ? pack_bf(v10) : __float_as_uint(v10);
                    w.y = PACK_OUT ? pack_bf(v11) : __float_as_uint(v11);
                    *(uint2*)(out + (size_t)r1 * 256 + c0) = w;
                    if (PACK_OUT) {
                        __half2 hv = __floats2half2_rn(v10, v11);
                        *(__half2*)(outh + (size_t)r1 * 256 + c0) = hv;
                    }
                }
            }
        }
    }
}

// ======================= launch =======================
extern "C" void kernel_launch(void* const* d_in, const int* in_sizes, int n_in,
                              void* d_out, int out_size) {
    const float* x = (const float*)d_in[0];
    const int* ei = (const int*)d_in[1];
    int E = in_sizes[1] / 2;
    const int* src = ei;
    const int* dst = ei + E;

    const float* Wl0 = (const float*)d_in[2];
    const float* bl0 = (const float*)d_in[3];
    const float* Wr0 = (const float*)d_in[4];
    const float* g0 = (const float*)d_in[5];
    const float* b0 = (const float*)d_in[6];
    const float* rm0 = (const float*)d_in[7];
    const float* rv0 = (const float*)d_in[8];
    const float* Wl1 = (const float*)d_in[9];
    const float* bl1 = (const float*)d_in[10];
    const float* Wr1 = (const float*)d_in[11];
    const float* g1 = (const float*)d_in[12];
    const float* b1 = (const float*)d_in[13];
    const float* rm1 = (const float*)d_in[14];
    const float* rv1 = (const float*)d_in[15];
    const float* Wl2 = (const float*)d_in[16];
    const float* bl2 = (const float*)d_in[17];
    const float* Wr2 = (const float*)d_in[18];
    const float* g2 = (const float*)d_in[19];
    const float* b2 = (const float*)d_in[20];
    const float* rm2 = (const float*)d_in[21];
    const float* rv2 = (const float*)d_in[22];

    uint32_t *X, *h1, *h2, *Mn;
    __half *Xh, *h1h, *h2h;
    float* P;
    __nv_bfloat16 *Bh, *Bl;
    cudaGetSymbolAddress((void**)&X, g_X);
    cudaGetSymbolAddress((void**)&Xh, g_Xh);
    cudaGetSymbolAddress((void**)&h1, g_h1);
    cudaGetSymbolAddress((void**)&h1h, g_h1h);
    cudaGetSymbolAddress((void**)&h2, g_h2);
    cudaGetSymbolAddress((void**)&h2h, g_h2h);
    cudaGetSymbolAddress((void**)&Mn, g_M);
    cudaGetSymbolAddress((void**)&P, g_P);
    cudaGetSymbolAddress((void**)&Bh, g_Bh);
    cudaGetSymbolAddress((void**)&Bl, g_Bl);
    __nv_bfloat16* Bh0 = Bh;
    __nv_bfloat16* Bh1 = Bh + 2 * 256 * 128;
    __nv_bfloat16* Bh2 = Bh1 + 2 * 256 * 256;
    __nv_bfloat16* Bl0 = Bl;
    __nv_bfloat16* Bl1 = Bl + 2 * 256 * 128;
    __nv_bfloat16* Bl2 = Bl1 + 2 * 256 * 256;
    __nv_bfloat16 *BhL0 = Bh0, *BhR0 = Bh0 + 256 * 128;
    __nv_bfloat16 *BlL0 = Bl0, *BlR0 = Bl0 + 256 * 128;
    __nv_bfloat16 *BhL1 = Bh1, *BhR1 = Bh1 + 256 * 256;
    __nv_bfloat16 *BlL1 = Bl1, *BlR1 = Bl1 + 256 * 256;
    __nv_bfloat16 *BhL2 = Bh2, *BhR2 = Bh2 + 256 * 256;
    __nv_bfloat16 *BlL2 = Bl2, *BlR2 = Bl2 + 256 * 256;

    cudaFuncSetAttribute(gemm_one<128, true, false, false>, cudaFuncAttributeMaxDynamicSharedMemorySize, GSMEM);
    cudaFuncSetAttribute(gemm_one<256, true, false, false>, cudaFuncAttributeMaxDynamicSharedMemorySize, GSMEM);
    cudaFuncSetAttribute(gemm_one<128, false, true, true>, cudaFuncAttributeMaxDynamicSharedMemorySize, GSMEM);
    cudaFuncSetAttribute(gemm_one<256, false, true, true>, cudaFuncAttributeMaxDynamicSharedMemorySize, GSMEM);
    cudaFuncSetAttribute(gemm_one<256, false, false, false>, cudaFuncAttributeMaxDynamicSharedMemorySize, GSMEM);

    cudaStream_t s1, s2;
    cudaStreamCreateWithFlags(&s1, cudaStreamNonBlocking);
    cudaStreamCreateWithFlags(&s2, cudaStreamNonBlocking);

    cudaEvent_t evRoot, evX, evP[3], evA0[3], evG0[3], evH[2];
    cudaEventCreateWithFlags(&evRoot, cudaEventDisableTiming);
    cudaEventCreateWithFlags(&evX, cudaEventDisableTiming);
    for (int i = 0; i < 3; i++) {
        cudaEventCreateWithFlags(&evP[i], cudaEventDisableTiming);
        cudaEventCreateWithFlags(&evA0[i], cudaEventDisableTiming);
        cudaEventCreateWithFlags(&evG0[i], cudaEventDisableTiming);
    }
    for (int i = 0; i < 2; i++) cudaEventCreateWithFlags(&evH[i], cudaEventDisableTiming);

    const int nScanBlocks = (NN + 255) / 256;
    dim3 ggH0(HALF0 / 128, 2);
    dim3 ggH1((NN - HALF0 + 127) / 128, 2);
    dim3 ggFull((NN + 127) / 128, 2);
    auto aggBlocks = [](int nodes, int nhalf) { return (nodes * nhalf * 32 + 255) / 256; };

    cudaEventRecord(evRoot, 0);
    cudaStreamWaitEvent(s1, evRoot, 0);
    cudaStreamWaitEvent(s2, evRoot, 0);

    // ---- s1: conversions + self-GEMM layer 0 ----
    conv_x_kernel<<<(NN * 128 + 255) / 256, 256, 0, s1>>>(x);
    cudaEventRecord(evX, s1);
    conv_w_kernel<<<(2 * 256 * 128 + 255) / 256, 256, 0, s1>>>(Wl0, Wr0, Bh0, Bl0, 128);
    conv_w_kernel<<<(2 * 256 * 256 + 255) / 256, 256, 0, s1>>>(Wl1, Wr1, Bh1, Bl1, 256);
    conv_w_kernel<<<(2 * 256 * 256 + 255) / 256, 256, 0, s1>>>(Wl2, Wr2, Bh2, Bl2, 256);
    gemm_one<128, true, false, false><<<ggFull, 256, GSMEM, s1>>>(
        X, BhR0, BlR0, nullptr, nullptr, nullptr, nullptr, nullptr, nullptr, P, nullptr, 0, NN);
    cudaEventRecord(evP[0], s1);

    // ---- main: CSR build ----
    zero_counts_kernel<<<(NN + 255) / 256, 256>>>();
    hist_kernel<<<(E + 255) / 256, 256>>>(dst, E);
    block_sums_kernel<<<nScanBlocks, 256>>>();
    scan_bsums_kernel<<<1, 256>>>(nScanBlocks);
    scan_final_kernel<<<nScanBlocks, 256>>>();
    scatter_kernel<<<(E + 255) / 256, 256>>>(src, dst, E);

    // =========== layer 0 ===========
    cudaStreamWaitEvent(0, evX, 0);
    agg_f16<1><<<aggBlocks(HALF0, 1), 256>>>(Xh, Mn, 0, HALF0);
    cudaEventRecord(evA0[0], 0);
    agg_f16<1><<<aggBlocks(NN - HALF0, 1), 256>>>(Xh, Mn, HALF0, NN);

    cudaStreamWaitEvent(s2, evA0[0], 0);
    cudaStreamWaitEvent(s2, evP[0], 0);
    gemm_one<128, false, true, true><<<ggH0, 256, GSMEM, s2>>>(
        Mn, BhL0, BlL0, P, bl0, g0, b0, rm0, rv0, h1, h1h, 0, NN);
    cudaEventRecord(evG0[0], s2);

    cudaStreamWaitEvent(0, evP[0], 0);
    gemm_one<128, false, true, true><<<ggH1, 256, GSMEM>>>(
        Mn, BhL0, BlL0, P, bl0, g0, b0, rm0, rv0, h1, h1h, HALF0, NN);
    cudaStreamWaitEvent(0, evG0[0], 0);
    cudaEventRecord(evH[0], 0);

    // s1: self-GEMM layer 1
    cudaStreamWaitEvent(s1, evH[0], 0);
    gemm_one<256, true, false, false><<<ggFull, 256, GSMEM, s1>>>(
        h1, BhR1, BlR1, nullptr, nullptr, nullptr, nullptr, nullptr, nullptr, P, nullptr, 0, NN);
    cudaEventRecord(evP[1], s1);

    // =========== layer 1 ===========
    agg_f16<2><<<aggBlocks(HALF0, 2), 256>>>(h1h, Mn, 0, HALF0);
    cudaEventRecord(evA0[1], 0);
    agg_f16<2><<<aggBlocks(NN - HALF0, 2), 256>>>(h1h, Mn, HALF0, NN);

    cudaStreamWaitEvent(s2, evA0[1], 0);
    cudaStreamWaitEvent(s2, evP[1], 0);
    gemm_one<256, false, true, true><<<ggH0, 256, GSMEM, s2>>>(
        Mn, BhL1, BlL1, P, bl1, g1, b1, rm1, rv1, h2, h2h, 0, NN);
    cudaEventRecord(evG0[1], s2);

    cudaStreamWaitEvent(0, evP[1], 0);
    gemm_one<256, false, true, true><<<ggH1, 256, GSMEM>>>(
        Mn, BhL1, BlL1, P, bl1, g1, b1, rm1, rv1, h2, h2h, HALF0, NN);
    cudaStreamWaitEvent(0, evG0[1], 0);
    cudaEventRecord(evH[1], 0);

    // s1: self-GEMM layer 2
    cudaStreamWaitEvent(s1, evH[1], 0);
    gemm_one<256, true, false, false><<<ggFull, 256, GSMEM, s1>>>(
        h2, BhR2, BlR2, nullptr, nullptr, nullptr, nullptr, nullptr, nullptr, P, nullptr, 0, NN);
    cudaEventRecord(evP[2], s1);

    // =========== layer 2 ===========
    agg_f16<2><<<aggBlocks(HALF0, 2), 256>>>(h2h, Mn, 0, HALF0);
    cudaEventRecord(evA0[2], 0);
    agg_f16<2><<<aggBlocks(NN - HALF0, 2), 256>>>(h2h, Mn, HALF0, NN);

    cudaStreamWaitEvent(s2, evA0[2], 0);
    cudaStreamWaitEvent(s2, evP[2], 0);
    gemm_one<256, false, false, false><<<ggH0, 256, GSMEM, s2>>>(
        Mn, BhL2, BlL2, P, bl2, g2, b2, rm2, rv2, d_out, nullptr, 0, NN);
    cudaEventRecord(evG0[2], s2);

    cudaStreamWaitEvent(0, evP[2], 0);
    gemm_one<256, false, false, false><<<ggH1, 256, GSMEM>>>(
        Mn, BhL2, BlL2, P, bl2, g2, b2, rm2, rv2, d_out, nullptr, HALF0, NN);
    cudaStreamWaitEvent(0, evG0[2], 0);

    cudaEventDestroy(evRoot);
    cudaEventDestroy(evX);
    for (int i = 0; i < 3; i++) {
        cudaEventDestroy(evP[i]);
        cudaEventDestroy(evA0[i]);
        cudaEventDestroy(evG0[i]);
    }
    for (int i = 0; i < 2; i++) cudaEventDestroy(evH[i]);
    cudaStreamDestroy(s1);
    cudaStreamDestroy(s2);
}

// round 10
// speedup vs baseline: 1.5968x; 1.5968x over previous
#include <cuda_runtime.h>
#include <cuda_fp16.h>
#include <cstdint>

#define NN 50000
#define EMAX 800000
#define EPS 1e-5f
#define HALF0 25088   // 196 * 128

__device__ __forceinline__ void cpasync16(uint32_t dst, const void* src) {
    asm volatile("cp.async.cg.shared.global [%0], [%1], 16;" :: "r"(dst), "l"(src));
}
__device__ __forceinline__ void cpcommit() { asm volatile("cp.async.commit_group;" ::: "memory"); }
__device__ __forceinline__ void cpwait0()  { asm volatile("cp.async.wait_group 0;" ::: "memory"); }

// ======================= scratch =======================
__device__ __half g_Xh[NN * 128];      // fp16 activation tables
__device__ __half g_h1h[NN * 256];
__device__ __half g_h2h[NN * 256];
__device__ __half g_Mh[NN * 256];      // fp16 mean
__device__ float  g_P[NN * 256];       // fp32 partial: x @ Wr
__device__ __align__(16) __half g_Bf[2 * 256 * 128 + 2 * 2 * 256 * 256];  // fp16 weights [mat][n][k]
__device__ int g_counts[NN];
__device__ int g_offsets[NN + 1];
__device__ int g_cursor[NN];
__device__ int g_esrc[EMAX];
__device__ int g_bsum[256];
__device__ int g_boff[256];

// ======================= CSR build =======================
__global__ void zero_counts_kernel() {
    int i = blockIdx.x * blockDim.x + threadIdx.x;
    if (i < NN) g_counts[i] = 0;
}
__global__ void hist_kernel(const int* __restrict__ dst, int E) {
    int e = blockIdx.x * blockDim.x + threadIdx.x;
    if (e < E) atomicAdd(&g_counts[dst[e]], 1);
}
__global__ void block_sums_kernel() {
    __shared__ int s[256];
    int i = blockIdx.x * 256 + threadIdx.x;
    s[threadIdx.x] = (i < NN) ? g_counts[i] : 0;
    __syncthreads();
    #pragma unroll
    for (int off = 128; off > 0; off >>= 1) {
        if (threadIdx.x < off) s[threadIdx.x] += s[threadIdx.x + off];
        __syncthreads();
    }
    if (threadIdx.x == 0) g_bsum[blockIdx.x] = s[0];
}
__global__ void scan_bsums_kernel(int nb) {
    __shared__ int s[256];
    int v = (threadIdx.x < nb) ? g_bsum[threadIdx.x] : 0;
    s[threadIdx.x] = v;
    __syncthreads();
    #pragma unroll
    for (int off = 1; off < 256; off <<= 1) {
        int t = (threadIdx.x >= off) ? s[threadIdx.x - off] : 0;
        __syncthreads();
        s[threadIdx.x] += t;
        __syncthreads();
    }
    if (threadIdx.x < nb) g_boff[threadIdx.x] = s[threadIdx.x] - v;
    if (threadIdx.x == 255) g_offsets[NN] = s[255];
}
__global__ void scan_final_kernel() {
    __shared__ int s[256];
    int i = blockIdx.x * 256 + threadIdx.x;
    int v = (i < NN) ? g_counts[i] : 0;
    s[threadIdx.x] = v;
    __syncthreads();
    #pragma unroll
    for (int off = 1; off < 256; off <<= 1) {
        int t = (threadIdx.x >= off) ? s[threadIdx.x - off] : 0;
        __syncthreads();
        s[threadIdx.x] += t;
        __syncthreads();
    }
    if (i < NN) {
        g_offsets[i] = g_boff[blockIdx.x] + s[threadIdx.x] - v;
        g_cursor[i] = 0;
    }
}
__global__ void scatter_kernel(const int* __restrict__ src, const int* __restrict__ dst, int E) {
    int e = blockIdx.x * blockDim.x + threadIdx.x;
    if (e < E) {
        int d = dst[e];
        int p = atomicAdd(&g_cursor[d], 1);
        g_esrc[g_offsets[d] + p] = src[e];
    }
}

// ======================= conversion =======================
__global__ void conv_x_kernel(const float* __restrict__ x) {
    int i = blockIdx.x * blockDim.x + threadIdx.x;
    if (i < NN * 128) g_Xh[i] = __float2half(x[i]);
}
__global__ void conv_w_kernel(const float* __restrict__ Wl, const float* __restrict__ Wr,
                              __half* __restrict__ Bf, int K) {
    int i = blockIdx.x * blockDim.x + threadIdx.x;
    int tot = 2 * 256 * K;
    if (i >= tot) return;
    int mat = i / (256 * K);
    int r = i - mat * 256 * K;
    int n = r / K;
    int k = r - n * K;
    const float* W = mat ? Wr : Wl;
    Bf[i] = __float2half(W[k * 256 + n]);
}

// ======================= mean aggregation (fp16) =======================
template <int NHALF>
__global__ __launch_bounds__(256) void agg_f16(const __half* __restrict__ h,
                                               __half* __restrict__ mean,
                                               int nodeBeg, int nodeEnd) {
    int gw = (blockIdx.x * blockDim.x + threadIdx.x) >> 5;
    int nNodes = nodeEnd - nodeBeg;
    if (gw >= nNodes * NHALF) return;
    int node, half;
    if (NHALF == 2) { node = nodeBeg + (gw >> 1); half = gw & 1; }
    else            { node = nodeBeg + gw;        half = 0; }
    int lane = threadIdx.x & 31;
    int beg = g_offsets[node], end = g_offsets[node + 1];

    const int RS = NHALF * 32;   // row stride in uint2 (4-half) units
    const uint2* base = reinterpret_cast<const uint2*>(h) + half * 32 + lane;

    float a0 = 0.f, a1 = 0.f, a2 = 0.f, a3 = 0.f;
    int e = beg;
    for (; e + 4 <= end; e += 4) {
        int s0 = g_esrc[e + 0];
        int s1 = g_esrc[e + 1];
        int s2 = g_esrc[e + 2];
        int s3 = g_esrc[e + 3];
        uint2 t0 = __ldg(base + (size_t)s0 * RS);
        uint2 t1 = __ldg(base + (size_t)s1 * RS);
        uint2 t2 = __ldg(base + (size_t)s2 * RS);
        uint2 t3 = __ldg(base + (size_t)s3 * RS);
        float2 f0a = __half22float2(*(const __half2*)&t0.x), f0b = __half22float2(*(const __half2*)&t0.y);
        float2 f1a = __half22float2(*(const __half2*)&t1.x), f1b = __half22float2(*(const __half2*)&t1.y);
        float2 f2a = __half22float2(*(const __half2*)&t2.x), f2b = __half22float2(*(const __half2*)&t2.y);
        float2 f3a = __half22float2(*(const __half2*)&t3.x), f3b = __half22float2(*(const __half2*)&t3.y);
        a0 += f0a.x + f1a.x + f2a.x + f3a.x;
        a1 += f0a.y + f1a.y + f2a.y + f3a.y;
        a2 += f0b.x + f1b.x + f2b.x + f3b.x;
        a3 += f0b.y + f1b.y + f2b.y + f3b.y;
    }
    for (; e < end; e++) {
        int s = g_esrc[e];
        uint2 t = __ldg(base + (size_t)s * RS);
        float2 fa = __half22float2(*(const __half2*)&t.x);
        float2 fb = __half22float2(*(const __half2*)&t.y);
        a0 += fa.x; a1 += fa.y; a2 += fb.x; a3 += fb.y;
    }

    int deg = end - beg;
    float inv = 1.0f / (float)(deg > 1 ? deg : 1);
    __half2 p0 = __floats2half2_rn(a0 * inv, a1 * inv);
    __half2 p1 = __floats2half2_rn(a2 * inv, a3 * inv);
    uint2 o;
    o.x = *(uint32_t*)&p0;
    o.y = *(uint32_t*)&p1;
    reinterpret_cast<uint2*>(mean)[(size_t)node * RS + half * 32 + lane] = o;
}

// ======================= fp16 mma.sync helper =======================
__device__ __forceinline__ void mma16816(float* c, const uint32_t* a, uint32_t b0, uint32_t b1) {
    asm("mma.sync.aligned.m16n8k16.row.col.f32.f16.f16.f32 "
        "{%0,%1,%2,%3}, {%4,%5,%6,%7}, {%8,%9}, {%0,%1,%2,%3};"
        : "+f"(c[0]), "+f"(c[1]), "+f"(c[2]), "+f"(c[3])
        : "r"(a[0]), "r"(a[1]), "r"(a[2]), "r"(a[3]), "r"(b0), "r"(b1));
}

// ======================= double-buffered fp16 GEMM =======================
#define SST 40
#define PLANE_B (128 * SST * 2)   // 10240 bytes per plane (A or B)
#define BUF_B   (2 * PLANE_B)     // 20480 bytes per buffer
#define GSMEM   (2 * BUF_B)       // 40960 bytes

template <int K, bool SELF, bool PACK_OUT, bool RELU>
__global__ __launch_bounds__(256, 2) void gemm_one(
    const __half* __restrict__ A,
    const __half* __restrict__ Bf,
    const float* __restrict__ P,
    const float* __restrict__ blv, const float* __restrict__ gam,
    const float* __restrict__ bet, const float* __restrict__ rm,
    const float* __restrict__ rv,
    void* __restrict__ outv, __half* __restrict__ outh, int rowOff, int M)
{
    extern __shared__ __align__(16) char dsm[];
    constexpr int NC = K / 32;

    int tid = threadIdx.x;
    int lane = tid & 31;
    int wid = tid >> 5;
    int g = lane >> 2;
    int tig = lane & 3;
    int wm = wid & 3;
    int wn = wid >> 2;
    int mBase = rowOff + blockIdx.x * 128;
    int nBase = blockIdx.y * 128;

    float acc[2][8][4];
    #pragma unroll
    for (int mt = 0; mt < 2; mt++)
        #pragma unroll
        for (int nt = 0; nt < 8; nt++)
            #pragma unroll
            for (int q = 0; q < 4; q++) acc[mt][nt][q] = 0.f;

    // B plane via cp.async: 128 rows x 32 halves (64B = 4x16B per row)
    auto stageB = [&](int kc, int buf) {
        char* base = dsm + buf * BUF_B;
        uint32_t dB = (uint32_t)__cvta_generic_to_shared(base + PLANE_B);
        #pragma unroll
        for (int i = 0; i < 2; i++) {
            int lin = tid + i * 256;
            int row = lin >> 2;
            int c8 = lin & 3;
            uint32_t doff = (uint32_t)(row * (SST * 2) + c8 * 16);
            cpasync16(dB + doff, Bf + (size_t)(nBase + row) * K + kc * 32 + c8 * 8);
        }
        cpcommit();
    };
    // A: 128 rows x 32 halves = 8192B; 2x16B per thread
    auto loadA = [&](int kc, uint4* pa) {
        #pragma unroll
        for (int i = 0; i < 2; i++) {
            int lin = tid + i * 256;
            int row = lin >> 2;
            int c8 = lin & 3;
            int grow = mBase + row;
            pa[i] = (grow < M)
                ? *(const uint4*)(A + (size_t)grow * K + kc * 32 + c8 * 8)
                : make_uint4(0u, 0u, 0u, 0u);
        }
    };
    auto storeA = [&](int buf, const uint4* pa) {
        char* base = dsm + buf * BUF_B;
        __half* sA = (__half*)base;
        #pragma unroll
        for (int i = 0; i < 2; i++) {
            int lin = tid + i * 256;
            int row = lin >> 2;
            int c8 = lin & 3;
            *(uint4*)&sA[row * SST + c8 * 8] = pa[i];
        }
    };

    uint4 pa[2];
    stageB(0, 0);
    loadA(0, pa);
    storeA(0, pa);
    cpwait0();
    __syncthreads();

    for (int kc = 0; kc < NC; kc++) {
        int cur = kc & 1;
        int nxt = cur ^ 1;
        bool more = (kc + 1 < NC);
        if (more) {
            stageB(kc + 1, nxt);
            loadA(kc + 1, pa);
        }
        {
            char* base = dsm + cur * BUF_B;
            const __half* sA = (const __half*)base;
            const __half* sB = (const __half*)(base + PLANE_B);
            #pragma unroll
            for (int ks = 0; ks < 2; ks++) {
                int k0 = ks * 16;
                uint32_t ah[2][4];
                #pragma unroll
                for (int mt = 0; mt < 2; mt++) {
                    int r0 = (wm * 32 + mt * 16 + g) * SST + k0 + 2 * tig;
                    ah[mt][0] = *(const uint32_t*)&sA[r0];
                    ah[mt][1] = *(const uint32_t*)&sA[r0 + 8 * SST];
                    ah[mt][2] = *(const uint32_t*)&sA[r0 + 8];
                    ah[mt][3] = *(const uint32_t*)&sA[r0 + 8 * SST + 8];
                }
                #pragma unroll
                for (int nt = 0; nt < 8; nt++) {
                    int b0 = (wn * 64 + nt * 8 + g) * SST + k0 + 2 * tig;
                    uint32_t bv0 = *(const uint32_t*)&sB[b0];
                    uint32_t bv1 = *(const uint32_t*)&sB[b0 + 8];
                    #pragma unroll
                    for (int mt = 0; mt < 2; mt++)
                        mma16816(acc[mt][nt], ah[mt], bv0, bv1);
                }
            }
        }
        if (more) {
            storeA(nxt, pa);
            cpwait0();
        }
        __syncthreads();
    }

    if (SELF) {
        float* out = (float*)outv;
        #pragma unroll
        for (int nt = 0; nt < 8; nt++) {
            int c0 = nBase + wn * 64 + nt * 8 + 2 * tig;
            #pragma unroll
            for (int mt = 0; mt < 2; mt++) {
                int r0 = mBase + wm * 32 + mt * 16 + g;
                int r1 = r0 + 8;
                if (r0 < M)
                    *(float2*)(out + (size_t)r0 * 256 + c0) = make_float2(acc[mt][nt][0], acc[mt][nt][1]);
                if (r1 < M)
                    *(float2*)(out + (size_t)r1 * 256 + c0) = make_float2(acc[mt][nt][2], acc[mt][nt][3]);
            }
        }
    } else {
        #pragma unroll
        for (int nt = 0; nt < 8; nt++) {
            int c0 = nBase + wn * 64 + nt * 8 + 2 * tig;
            int c1 = c0 + 1;
            float sc0 = gam[c0] * rsqrtf(rv[c0] + EPS);
            float sh0 = (blv[c0] - rm[c0]) * sc0 + bet[c0];
            float sc1 = gam[c1] * rsqrtf(rv[c1] + EPS);
            float sh1 = (blv[c1] - rm[c1]) * sc1 + bet[c1];
            #pragma unroll
            for (int mt = 0; mt < 2; mt++) {
                int r0 = mBase + wm * 32 + mt * 16 + g;
                int r1 = r0 + 8;
                if (r0 < M) {
                    float2 p = *(const float2*)(P + (size_t)r0 * 256 + c0);
                    float v00 = (acc[mt][nt][0] + p.x) * sc0 + sh0;
                    float v01 = (acc[mt][nt][1] + p.y) * sc1 + sh1;
                    if (RELU) { v00 = fmaxf(v00, 0.f); v01 = fmaxf(v01, 0.f); }
                    if (PACK_OUT) {
                        __half2 hv = __floats2half2_rn(v00, v01);
                        *(__half2*)(outh + (size_t)r0 * 256 + c0) = hv;
                    } else {
                        *(float2*)((float*)outv + (size_t)r0 * 256 + c0) = make_float2(v00, v01);
                    }
                }
                if (r1 < M) {
                    float2 p = *(const float2*)(P + (size_t)r1 * 256 + c0);
                    float v10 = (acc[mt][nt][2] + p.x) * sc0 + sh0;
                    float v11 = (acc[mt][nt][3] + p.y) * sc1 + sh1;
                    if (RELU) { v10 = fmaxf(v10, 0.f); v11 = fmaxf(v11, 0.f); }
                    if (PACK_OUT) {
                        __half2 hv = __floats2half2_rn(v10, v11);
                        *(__half2*)(outh + (size_t)r1 * 256 + c0) = hv;
                    } else {
                        *(float2*)((float*)outv + (size_t)r1 * 256 + c0) = make_float2(v10, v11);
                    }
                }
            }
        }
    }
}

// ======================= launch =======================
extern "C" void kernel_launch(void* const* d_in, const int* in_sizes, int n_in,
                              void* d_out, int out_size) {
    const float* x = (const float*)d_in[0];
    const int* ei = (const int*)d_in[1];
    int E = in_sizes[1] / 2;
    const int* src = ei;
    const int* dst = ei + E;

    const float* Wl0 = (const float*)d_in[2];
    const float* bl0 = (const float*)d_in[3];
    const float* Wr0 = (const float*)d_in[4];
    const float* g0 = (const float*)d_in[5];
    const float* b0 = (const float*)d_in[6];
    const float* rm0 = (const float*)d_in[7];
    const float* rv0 = (const float*)d_in[8];
    const float* Wl1 = (const float*)d_in[9];
    const float* bl1 = (const float*)d_in[10];
    const float* Wr1 = (const float*)d_in[11];
    const float* g1 = (const float*)d_in[12];
    const float* b1 = (const float*)d_in[13];
    const float* rm1 = (const float*)d_in[14];
    const float* rv1 = (const float*)d_in[15];
    const float* Wl2 = (const float*)d_in[16];
    const float* bl2 = (const float*)d_in[17];
    const float* Wr2 = (const float*)d_in[18];
    const float* g2 = (const float*)d_in[19];
    const float* b2 = (const float*)d_in[20];
    const float* rm2 = (const float*)d_in[21];
    const float* rv2 = (const float*)d_in[22];

    __half *Xh, *h1h, *h2h, *Mh, *Bf;
    float* P;
    cudaGetSymbolAddress((void**)&Xh, g_Xh);
    cudaGetSymbolAddress((void**)&h1h, g_h1h);
    cudaGetSymbolAddress((void**)&h2h, g_h2h);
    cudaGetSymbolAddress((void**)&Mh, g_Mh);
    cudaGetSymbolAddress((void**)&P, g_P);
    cudaGetSymbolAddress((void**)&Bf, g_Bf);
    __half* Bf0 = Bf;
    __half* Bf1 = Bf0 + 2 * 256 * 128;
    __half* Bf2 = Bf1 + 2 * 256 * 256;
    __half *BfL0 = Bf0, *BfR0 = Bf0 + 256 * 128;
    __half *BfL1 = Bf1, *BfR1 = Bf1 + 256 * 256;
    __half *BfL2 = Bf2, *BfR2 = Bf2 + 256 * 256;

    cudaStream_t s1, s2;
    cudaStreamCreateWithFlags(&s1, cudaStreamNonBlocking);
    cudaStreamCreateWithFlags(&s2, cudaStreamNonBlocking);

    cudaEvent_t evRoot, evX, evP[3], evA0[3], evG0[3], evH[2];
    cudaEventCreateWithFlags(&evRoot, cudaEventDisableTiming);
    cudaEventCreateWithFlags(&evX, cudaEventDisableTiming);
    for (int i = 0; i < 3; i++) {
        cudaEventCreateWithFlags(&evP[i], cudaEventDisableTiming);
        cudaEventCreateWithFlags(&evA0[i], cudaEventDisableTiming);
        cudaEventCreateWithFlags(&evG0[i], cudaEventDisableTiming);
    }
    for (int i = 0; i < 2; i++) cudaEventCreateWithFlags(&evH[i], cudaEventDisableTiming);

    const int nScanBlocks = (NN + 255) / 256;
    dim3 ggH0(HALF0 / 128, 2);
    dim3 ggH1((NN - HALF0 + 127) / 128, 2);
    dim3 ggFull((NN + 127) / 128, 2);
    auto aggBlocks = [](int nodes, int nhalf) { return (nodes * nhalf * 32 + 255) / 256; };

    cudaEventRecord(evRoot, 0);
    cudaStreamWaitEvent(s1, evRoot, 0);
    cudaStreamWaitEvent(s2, evRoot, 0);

    // ---- s1: conversions + self-GEMM layer 0 ----
    conv_x_kernel<<<(NN * 128 + 255) / 256, 256, 0, s1>>>(x);
    cudaEventRecord(evX, s1);
    conv_w_kernel<<<(2 * 256 * 128 + 255) / 256, 256, 0, s1>>>(Wl0, Wr0, Bf0, 128);
    conv_w_kernel<<<(2 * 256 * 256 + 255) / 256, 256, 0, s1>>>(Wl1, Wr1, Bf1, 256);
    conv_w_kernel<<<(2 * 256 * 256 + 255) / 256, 256, 0, s1>>>(Wl2, Wr2, Bf2, 256);
    gemm_one<128, true, false, false><<<ggFull, 256, GSMEM, s1>>>(
        Xh, BfR0, nullptr, nullptr, nullptr, nullptr, nullptr, nullptr, P, nullptr, 0, NN);
    cudaEventRecord(evP[0], s1);

    // ---- main: CSR build ----
    zero_counts_kernel<<<(NN + 255) / 256, 256>>>();
    hist_kernel<<<(E + 255) / 256, 256>>>(dst, E);
    block_sums_kernel<<<nScanBlocks, 256>>>();
    scan_bsums_kernel<<<1, 256>>>(nScanBlocks);
    scan_final_kernel<<<nScanBlocks, 256>>>();
    scatter_kernel<<<(E + 255) / 256, 256>>>(src, dst, E);

    // =========== layer 0 ===========
    cudaStreamWaitEvent(0, evX, 0);
    agg_f16<1><<<aggBlocks(HALF0, 1), 256>>>(Xh, Mh, 0, HALF0);
    cudaEventRecord(evA0[0], 0);
    agg_f16<1><<<aggBlocks(NN - HALF0, 1), 256>>>(Xh, Mh, HALF0, NN);

    cudaStreamWaitEvent(s2, evA0[0], 0);
    cudaStreamWaitEvent(s2, evP[0], 0);
    gemm_one<128, false, true, true><<<ggH0, 256, GSMEM, s2>>>(
        Mh, BfL0, P, bl0, g0, b0, rm0, rv0, nullptr, h1h, 0, NN);
    cudaEventRecord(evG0[0], s2);

    cudaStreamWaitEvent(0, evP[0], 0);
    gemm_one<128, false, true, true><<<ggH1, 256, GSMEM>>>(
        Mh, BfL0, P, bl0, g0, b0, rm0, rv0, nullptr, h1h, HALF0, NN);
    cudaStreamWaitEvent(0, evG0[0], 0);
    cudaEventRecord(evH[0], 0);

    // s1: self-GEMM layer 1
    cudaStreamWaitEvent(s1, evH[0], 0);
    gemm_one<256, true, false, false><<<ggFull, 256, GSMEM, s1>>>(
        h1h, BfR1, nullptr, nullptr, nullptr, nullptr, nullptr, nullptr, P, nullptr, 0, NN);
    cudaEventRecord(evP[1], s1);

    // =========== layer 1 ===========
    agg_f16<2><<<aggBlocks(HALF0, 2), 256>>>(h1h, Mh, 0, HALF0);
    cudaEventRecord(evA0[1], 0);
    agg_f16<2><<<aggBlocks(NN - HALF0, 2), 256>>>(h1h, Mh, HALF0, NN);

    cudaStreamWaitEvent(s2, evA0[1], 0);
    cudaStreamWaitEvent(s2, evP[1], 0);
    gemm_one<256, false, true, true><<<ggH0, 256, GSMEM, s2>>>(
        Mh, BfL1, P, bl1, g1, b1, rm1, rv1, nullptr, h2h, 0, NN);
    cudaEventRecord(evG0[1], s2);

    cudaStreamWaitEvent(0, evP[1], 0);
    gemm_one<256, false, true, true><<<ggH1, 256, GSMEM>>>(
        Mh, BfL1, P, bl1, g1, b1, rm1, rv1, nullptr, h2h, HALF0, NN);
    cudaStreamWaitEvent(0, evG0[1], 0);
    cudaEventRecord(evH[1], 0);

    // s1: self-GEMM layer 2
    cudaStreamWaitEvent(s1, evH[1], 0);
    gemm_one<256, true, false, false><<<ggFull, 256, GSMEM, s1>>>(
        h2h, BfR2, nullptr, nullptr, nullptr, nullptr, nullptr, nullptr, P, nullptr, 0, NN);
    cudaEventRecord(evP[2], s1);

    // =========== layer 2 ===========
    agg_f16<2><<<aggBlocks(HALF0, 2), 256>>>(h2h, Mh, 0, HALF0);
    cudaEventRecord(evA0[2], 0);
    agg_f16<2><<<aggBlocks(NN - HALF0, 2), 256>>>(h2h, Mh, HALF0, NN);

    cudaStreamWaitEvent(s2, evA0[2], 0);
    cudaStreamWaitEvent(s2, evP[2], 0);
    gemm_one<256, false, false, false><<<ggH0, 256, GSMEM, s2>>>(
        Mh, BfL2, P, bl2, g2, b2, rm2, rv2, d_out, nullptr, 0, NN);
    cudaEventRecord(evG0[2], s2);

    cudaStreamWaitEvent(0, evP[2], 0);
    gemm_one<256, false, false, false><<<ggH1, 256, GSMEM>>>(
        Mh, BfL2, P, bl2, g2, b2, rm2, rv2, d_out, nullptr, HALF0, NN);
    cudaStreamWaitEvent(0, evG0[2], 0);

    cudaEventDestroy(evRoot);
    cudaEventDestroy(evX);
    for (int i = 0; i < 3; i++) {
        cudaEventDestroy(evP[i]);
        cudaEventDestroy(evA0[i]);
        cudaEventDestroy(evG0[i]);
    }
    for (int i = 0; i < 2; i++) cudaEventDestroy(evH[i]);
    cudaStreamDestroy(s1);
    cudaStreamDestroy(s2);
}

// round 11
// speedup vs baseline: 1.6942x; 1.0610x over previous
#include <cuda_runtime.h>
#include <cuda_fp16.h>
#include <cstdint>

#define NN 50000
#define EMAX 800000
#define EPS 1e-5f
#define HALF0 25088   // 196 * 128

__device__ __forceinline__ void cpasync16(uint32_t dst, const void* src) {
    asm volatile("cp.async.cg.shared.global [%0], [%1], 16;" :: "r"(dst), "l"(src));
}
// zfill variant: src_size 0 -> zero fill (src not read)
__device__ __forceinline__ void cpasync16z(uint32_t dst, const void* src, int size) {
    asm volatile("cp.async.cg.shared.global [%0], [%1], 16, %2;" :: "r"(dst), "l"(src), "r"(size));
}
__device__ __forceinline__ void cpcommit() { asm volatile("cp.async.commit_group;" ::: "memory"); }
__device__ __forceinline__ void cpwait0() { asm volatile("cp.async.wait_group 0;" ::: "memory"); }
__device__ __forceinline__ void cpwait1() { asm volatile("cp.async.wait_group 1;" ::: "memory"); }
__device__ __forceinline__ void cpwait2() { asm volatile("cp.async.wait_group 2;" ::: "memory"); }

// ======================= scratch =======================
__device__ __half g_Xh[NN * 128];
__device__ __half g_h1h[NN * 256];
__device__ __half g_h2h[NN * 256];
__device__ __half g_Mh[NN * 256];
__device__ float  g_P[NN * 256];
__device__ __align__(16) __half g_Bf[2 * 256 * 128 + 2 * 2 * 256 * 256];
__device__ int g_counts[NN];
__device__ int g_offsets[NN + 1];
__device__ int g_cursor[NN];
__device__ int g_esrc[EMAX];
__device__ int g_bsum[256];
__device__ int g_boff[256];

// ======================= CSR build =======================
__global__ void zero_counts_kernel() {
    int i = blockIdx.x * blockDim.x + threadIdx.x;
    if (i < NN) g_counts[i] = 0;
}
__global__ void hist_kernel(const int* __restrict__ dst, int E) {
    int e = blockIdx.x * blockDim.x + threadIdx.x;
    if (e < E) atomicAdd(&g_counts[dst[e]], 1);
}
__global__ void block_sums_kernel() {
    __shared__ int s[256];
    int i = blockIdx.x * 256 + threadIdx.x;
    s[threadIdx.x] = (i < NN) ? g_counts[i] : 0;
    __syncthreads();
    #pragma unroll
    for (int off = 128; off > 0; off >>= 1) {
        if (threadIdx.x < off) s[threadIdx.x] += s[threadIdx.x + off];
        __syncthreads();
    }
    if (threadIdx.x == 0) g_bsum[blockIdx.x] = s[0];
}
__global__ void scan_bsums_kernel(int nb) {
    __shared__ int s[256];
    int v = (threadIdx.x < nb) ? g_bsum[threadIdx.x] : 0;
    s[threadIdx.x] = v;
    __syncthreads();
    #pragma unroll
    for (int off = 1; off < 256; off <<= 1) {
        int t = (threadIdx.x >= off) ? s[threadIdx.x - off] : 0;
        __syncthreads();
        s[threadIdx.x] += t;
        __syncthreads();
    }
    if (threadIdx.x < nb) g_boff[threadIdx.x] = s[threadIdx.x] - v;
    if (threadIdx.x == 255) g_offsets[NN] = s[255];
}
__global__ void scan_final_kernel() {
    __shared__ int s[256];
    int i = blockIdx.x * 256 + threadIdx.x;
    int v = (i < NN) ? g_counts[i] : 0;
    s[threadIdx.x] = v;
    __syncthreads();
    #pragma unroll
    for (int off = 1; off < 256; off <<= 1) {
        int t = (threadIdx.x >= off) ? s[threadIdx.x - off] : 0;
        __syncthreads();
        s[threadIdx.x] += t;
        __syncthreads();
    }
    if (i < NN) {
        g_offsets[i] = g_boff[blockIdx.x] + s[threadIdx.x] - v;
        g_cursor[i] = 0;
    }
}
__global__ void scatter_kernel(const int* __restrict__ src, const int* __restrict__ dst, int E) {
    int e = blockIdx.x * blockDim.x + threadIdx.x;
    if (e < E) {
        int d = dst[e];
        int p = atomicAdd(&g_cursor[d], 1);
        g_esrc[g_offsets[d] + p] = src[e];
    }
}

// ======================= conversion =======================
__global__ void conv_x_kernel(const float* __restrict__ x) {
    int i = blockIdx.x * blockDim.x + threadIdx.x;
    if (i < NN * 128) g_Xh[i] = __float2half(x[i]);
}
__global__ void conv_w_kernel(const float* __restrict__ Wl, const float* __restrict__ Wr,
                              __half* __restrict__ Bf, int K) {
    int i = blockIdx.x * blockDim.x + threadIdx.x;
    int tot = 2 * 256 * K;
    if (i >= tot) return;
    int mat = i / (256 * K);
    int r = i - mat * 256 * K;
    int n = r / K;
    int k = r - n * K;
    const float* W = mat ? Wr : Wl;
    Bf[i] = __float2half(W[k * 256 + n]);
}

// ======================= mean aggregation: one warp per node =======================
// WIDE=false: K=128, uint2 (8B)/lane -> 256B row. WIDE=true: K=256, uint4 (16B)/lane -> 512B row.
template <bool WIDE>
__global__ __launch_bounds__(256) void agg_f16(const __half* __restrict__ h,
                                               __half* __restrict__ mean,
                                               int nodeBeg, int nodeEnd) {
    int w = (blockIdx.x * blockDim.x + threadIdx.x) >> 5;
    int node = nodeBeg + w;
    if (node >= nodeEnd) return;
    int lane = threadIdx.x & 31;
    int beg = g_offsets[node], end = g_offsets[node + 1];

    if (WIDE) {
        const uint4* base = reinterpret_cast<const uint4*>(h) + lane;
        float a0 = 0.f, a1 = 0.f, a2 = 0.f, a3 = 0.f, a4 = 0.f, a5 = 0.f, a6 = 0.f, a7 = 0.f;
        int e = beg;
        for (; e + 2 <= end; e += 2) {
            int s0 = g_esrc[e];
            int s1 = g_esrc[e + 1];
            uint4 t0 = __ldg(base + (size_t)s0 * 32);
            uint4 t1 = __ldg(base + (size_t)s1 * 32);
            float2 f;
            f = __half22float2(*(const __half2*)&t0.x); a0 += f.x; a1 += f.y;
            f = __half22float2(*(const __half2*)&t0.y); a2 += f.x; a3 += f.y;
            f = __half22float2(*(const __half2*)&t0.z); a4 += f.x; a5 += f.y;
            f = __half22float2(*(const __half2*)&t0.w); a6 += f.x; a7 += f.y;
            f = __half22float2(*(const __half2*)&t1.x); a0 += f.x; a1 += f.y;
            f = __half22float2(*(const __half2*)&t1.y); a2 += f.x; a3 += f.y;
            f = __half22float2(*(const __half2*)&t1.z); a4 += f.x; a5 += f.y;
            f = __half22float2(*(const __half2*)&t1.w); a6 += f.x; a7 += f.y;
        }
        for (; e < end; e++) {
            int s = g_esrc[e];
            uint4 t = __ldg(base + (size_t)s * 32);
            float2 f;
            f = __half22float2(*(const __half2*)&t.x); a0 += f.x; a1 += f.y;
            f = __half22float2(*(const __half2*)&t.y); a2 += f.x; a3 += f.y;
            f = __half22float2(*(const __half2*)&t.z); a4 += f.x; a5 += f.y;
            f = __half22float2(*(const __half2*)&t.w); a6 += f.x; a7 += f.y;
        }
        int deg = end - beg;
        float inv = 1.0f / (float)(deg > 1 ? deg : 1);
        __half2 p0 = __floats2half2_rn(a0 * inv, a1 * inv);
        __half2 p1 = __floats2half2_rn(a2 * inv, a3 * inv);
        __half2 p2 = __floats2half2_rn(a4 * inv, a5 * inv);
        __half2 p3 = __floats2half2_rn(a6 * inv, a7 * inv);
        uint4 o;
        o.x = *(uint32_t*)&p0; o.y = *(uint32_t*)&p1;
        o.z = *(uint32_t*)&p2; o.w = *(uint32_t*)&p3;
        reinterpret_cast<uint4*>(mean)[(size_t)node * 32 + lane] = o;
    } else {
        const uint2* base = reinterpret_cast<const uint2*>(h) + lane;
        float a0 = 0.f, a1 = 0.f, a2 = 0.f, a3 = 0.f;
        int e = beg;
        for (; e + 2 <= end; e += 2) {
            int s0 = g_esrc[e];
            int s1 = g_esrc[e + 1];
            uint2 t0 = __ldg(base + (size_t)s0 * 32);
            uint2 t1 = __ldg(base + (size_t)s1 * 32);
            float2 f;
            f = __half22float2(*(const __half2*)&t0.x); a0 += f.x; a1 += f.y;
            f = __half22float2(*(const __half2*)&t0.y); a2 += f.x; a3 += f.y;
            f = __half22float2(*(const __half2*)&t1.x); a0 += f.x; a1 += f.y;
            f = __half22float2(*(const __half2*)&t1.y); a2 += f.x; a3 += f.y;
        }
        for (; e < end; e++) {
            int s = g_esrc[e];
            uint2 t = __ldg(base + (size_t)s * 32);
            float2 f;
            f = __half22float2(*(const __half2*)&t.x); a0 += f.x; a1 += f.y;
            f = __half22float2(*(const __half2*)&t.y); a2 += f.x; a3 += f.y;
        }
        int deg = end - beg;
        float inv = 1.0f / (float)(deg > 1 ? deg : 1);
        __half2 p0 = __floats2half2_rn(a0 * inv, a1 * inv);
        __half2 p1 = __floats2half2_rn(a2 * inv, a3 * inv);
        uint2 o;
        o.x = *(uint32_t*)&p0; o.y = *(uint32_t*)&p1;
        reinterpret_cast<uint2*>(mean)[(size_t)node * 32 + lane] = o;
    }
}

// ======================= fp16 mma.sync helper =======================
__device__ __forceinline__ void mma16816(float* c, const uint32_t* a, uint32_t b0, uint32_t b1) {
    asm("mma.sync.aligned.m16n8k16.row.col.f32.f16.f16.f32 "
        "{%0,%1,%2,%3}, {%4,%5,%6,%7}, {%8,%9}, {%0,%1,%2,%3};"
        : "+f"(c[0]), "+f"(c[1]), "+f"(c[2]), "+f"(c[3])
        : "r"(a[0]), "r"(a[1]), "r"(a[2]), "r"(a[3]), "r"(b0), "r"(b1));
}

// ======================= 3-stage cp.async fp16 GEMM =======================
#define SST 40
#define PLANE_B (128 * SST * 2)   // 10240 bytes per plane
#define BUF_B   (2 * PLANE_B)     // 20480 bytes per stage (A + B)
#define NSTAGE  3
#define GSMEM   (NSTAGE * BUF_B)  // 61440 bytes

template <int K, bool SELF, bool PACK_OUT, bool RELU>
__global__ __launch_bounds__(256, 2) void gemm_one(
    const __half* __restrict__ A,
    const __half* __restrict__ Bf,
    const float* __restrict__ P,
    const float* __restrict__ blv, const float* __restrict__ gam,
    const float* __restrict__ bet, const float* __restrict__ rm,
    const float* __restrict__ rv,
    void* __restrict__ outv, __half* __restrict__ outh, int rowOff, int M)
{
    extern __shared__ __align__(16) char dsm[];
    constexpr int NC = K / 32;

    int tid = threadIdx.x;
    int lane = tid & 31;
    int wid = tid >> 5;
    int g = lane >> 2;
    int tig = lane & 3;
    int wm = wid & 3;
    int wn = wid >> 2;
    int mBase = rowOff + blockIdx.x * 128;
    int nBase = blockIdx.y * 128;

    float acc[2][8][4];
    #pragma unroll
    for (int mt = 0; mt < 2; mt++)
        #pragma unroll
        for (int nt = 0; nt < 8; nt++)
            #pragma unroll
            for (int q = 0; q < 4; q++) acc[mt][nt][q] = 0.f;

    // one stage = A plane (128x32 halves) + B plane, each 8KB payload in 10240B plane.
    // 512 x 16B per plane; 2 cp.async per thread per plane.
    auto stageAB = [&](int kc, int buf) {
        char* base = dsm + buf * BUF_B;
        uint32_t dA = (uint32_t)__cvta_generic_to_shared(base);
        uint32_t dB = (uint32_t)__cvta_generic_to_shared(base + PLANE_B);
        #pragma unroll
        for (int i = 0; i < 2; i++) {
            int lin = tid + i * 256;
            int row = lin >> 2;
            int c8 = lin & 3;
            uint32_t doff = (uint32_t)(row * (SST * 2) + c8 * 16);
            int grow = mBase + row;
            int ok = (grow < M);
            int gr = ok ? grow : (M - 1);
            cpasync16z(dA + doff, A + (size_t)gr * K + kc * 32 + c8 * 8, ok ? 16 : 0);
            cpasync16(dB + doff, Bf + (size_t)(nBase + row) * K + kc * 32 + c8 * 8);
        }
        cpcommit();
    };

    stageAB(0, 0);
    if (NC > 1) stageAB(1, 1);

    for (int kc = 0; kc < NC; kc++) {
        if (kc + 2 < NC) stageAB(kc + 2, (kc + 2) % NSTAGE);
        int rem = NC - 1 - kc;
        if (rem >= 2) cpwait2();
        else if (rem == 1) cpwait1();
        else cpwait0();
        __syncthreads();
        {
            char* base = dsm + (kc % NSTAGE) * BUF_B;
            const __half* sA = (const __half*)base;
            const __half* sB = (const __half*)(base + PLANE_B);
            #pragma unroll
            for (int ks = 0; ks < 2; ks++) {
                int k0 = ks * 16;
                uint32_t ah[2][4];
                #pragma unroll
                for (int mt = 0; mt < 2; mt++) {
                    int r0 = (wm * 32 + mt * 16 + g) * SST + k0 + 2 * tig;
                    ah[mt][0] = *(const uint32_t*)&sA[r0];
                    ah[mt][1] = *(const uint32_t*)&sA[r0 + 8 * SST];
                    ah[mt][2] = *(const uint32_t*)&sA[r0 + 8];
                    ah[mt][3] = *(const uint32_t*)&sA[r0 + 8 * SST + 8];
                }
                #pragma unroll
                for (int nt = 0; nt < 8; nt++) {
                    int b0 = (wn * 64 + nt * 8 + g) * SST + k0 + 2 * tig;
                    uint32_t bv0 = *(const uint32_t*)&sB[b0];
                    uint32_t bv1 = *(const uint32_t*)&sB[b0 + 8];
                    #pragma unroll
                    for (int mt = 0; mt < 2; mt++)
                        mma16816(acc[mt][nt], ah[mt], bv0, bv1);
                }
            }
        }
        __syncthreads();
    }

    if (SELF) {
        float* out = (float*)outv;
        #pragma unroll
        for (int nt = 0; nt < 8; nt++) {
            int c0 = nBase + wn * 64 + nt * 8 + 2 * tig;
            #pragma unroll
            for (int mt = 0; mt < 2; mt++) {
                int r0 = mBase + wm * 32 + mt * 16 + g;
                int r1 = r0 + 8;
                if (r0 < M)
                    *(float2*)(out + (size_t)r0 * 256 + c0) = make_float2(acc[mt][nt][0], acc[mt][nt][1]);
                if (r1 < M)
                    *(float2*)(out + (size_t)r1 * 256 + c0) = make_float2(acc[mt][nt][2], acc[mt][nt][3]);
            }
        }
    } else {
        #pragma unroll
        for (int nt = 0; nt < 8; nt++) {
            int c0 = nBase + wn * 64 + nt * 8 + 2 * tig;
            int c1 = c0 + 1;
            float sc0 = gam[c0] * rsqrtf(rv[c0] + EPS);
            float sh0 = (blv[c0] - rm[c0]) * sc0 + bet[c0];
            float sc1 = gam[c1] * rsqrtf(rv[c1] + EPS);
            float sh1 = (blv[c1] - rm[c1]) * sc1 + bet[c1];
            #pragma unroll
            for (int mt = 0; mt < 2; mt++) {
                int r0 = mBase + wm * 32 + mt * 16 + g;
                int r1 = r0 + 8;
                if (r0 < M) {
                    float2 p = *(const float2*)(P + (size_t)r0 * 256 + c0);
                    float v00 = (acc[mt][nt][0] + p.x) * sc0 + sh0;
                    float v01 = (acc[mt][nt][1] + p.y) * sc1 + sh1;
                    if (RELU) { v00 = fmaxf(v00, 0.f); v01 = fmaxf(v01, 0.f); }
                    if (PACK_OUT) {
                        __half2 hv = __floats2half2_rn(v00, v01);
                        *(__half2*)(outh + (size_t)r0 * 256 + c0) = hv;
                    } else {
                        *(float2*)((float*)outv + (size_t)r0 * 256 + c0) = make_float2(v00, v01);
                    }
                }
                if (r1 < M) {
                    float2 p = *(const float2*)(P + (size_t)r1 * 256 + c0);
                    float v10 = (acc[mt][nt][2] + p.x) * sc0 + sh0;
                    float v11 = (acc[mt][nt][3] + p.y) * sc1 + sh1;
                    if (RELU) { v10 = fmaxf(v10, 0.f); v11 = fmaxf(v11, 0.f); }
                    if (PACK_OUT) {
                        __half2 hv = __floats2half2_rn(v10, v11);
                        *(__half2*)(outh + (size_t)r1 * 256 + c0) = hv;
                    } else {
                        *(float2*)((float*)outv + (size_t)r1 * 256 + c0) = make_float2(v10, v11);
                    }
                }
            }
        }
    }
}

// ======================= launch =======================
extern "C" void kernel_launch(void* const* d_in, const int* in_sizes, int n_in,
                              void* d_out, int out_size) {
    const float* x = (const float*)d_in[0];
    const int* ei = (const int*)d_in[1];
    int E = in_sizes[1] / 2;
    const int* src = ei;
    const int* dst = ei + E;

    const float* Wl0 = (const float*)d_in[2];
    const float* bl0 = (const float*)d_in[3];
    const float* Wr0 = (const float*)d_in[4];
    const float* g0 = (const float*)d_in[5];
    const float* b0 = (const float*)d_in[6];
    const float* rm0 = (const float*)d_in[7];
    const float* rv0 = (const float*)d_in[8];
    const float* Wl1 = (const float*)d_in[9];
    const float* bl1 = (const float*)d_in[10];
    const float* Wr1 = (const float*)d_in[11];
    const float* g1 = (const float*)d_in[12];
    const float* b1 = (const float*)d_in[13];
    const float* rm1 = (const float*)d_in[14];
    const float* rv1 = (const float*)d_in[15];
    const float* Wl2 = (const float*)d_in[16];
    const float* bl2 = (const float*)d_in[17];
    const float* Wr2 = (const float*)d_in[18];
    const float* g2 = (const float*)d_in[19];
    const float* b2 = (const float*)d_in[20];
    const float* rm2 = (const float*)d_in[21];
    const float* rv2 = (const float*)d_in[22];

    __half *Xh, *h1h, *h2h, *Mh, *Bf;
    float* P;
    cudaGetSymbolAddress((void**)&Xh, g_Xh);
    cudaGetSymbolAddress((void**)&h1h, g_h1h);
    cudaGetSymbolAddress((void**)&h2h, g_h2h);
    cudaGetSymbolAddress((void**)&Mh, g_Mh);
    cudaGetSymbolAddress((void**)&P, g_P);
    cudaGetSymbolAddress((void**)&Bf, g_Bf);
    __half* Bf0 = Bf;
    __half* Bf1 = Bf0 + 2 * 256 * 128;
    __half* Bf2 = Bf1 + 2 * 256 * 256;
    __half *BfL0 = Bf0, *BfR0 = Bf0 + 256 * 128;
    __half *BfL1 = Bf1, *BfR1 = Bf1 + 256 * 256;
    __half *BfL2 = Bf2, *BfR2 = Bf2 + 256 * 256;

    cudaFuncSetAttribute(gemm_one<128, true, false, false>, cudaFuncAttributeMaxDynamicSharedMemorySize, GSMEM);
    cudaFuncSetAttribute(gemm_one<256, true, false, false>, cudaFuncAttributeMaxDynamicSharedMemorySize, GSMEM);
    cudaFuncSetAttribute(gemm_one<128, false, true, true>, cudaFuncAttributeMaxDynamicSharedMemorySize, GSMEM);
    cudaFuncSetAttribute(gemm_one<256, false, true, true>, cudaFuncAttributeMaxDynamicSharedMemorySize, GSMEM);
    cudaFuncSetAttribute(gemm_one<256, false, false, false>, cudaFuncAttributeMaxDynamicSharedMemorySize, GSMEM);

    cudaStream_t s1, s2;
    cudaStreamCreateWithFlags(&s1, cudaStreamNonBlocking);
    cudaStreamCreateWithFlags(&s2, cudaStreamNonBlocking);

    cudaEvent_t evRoot, evX, evP[3], evA0[3], evG0[3], evH[2];
    cudaEventCreateWithFlags(&evRoot, cudaEventDisableTiming);
    cudaEventCreateWithFlags(&evX, cudaEventDisableTiming);
    for (int i = 0; i < 3; i++) {
        cudaEventCreateWithFlags(&evP[i], cudaEventDisableTiming);
        cudaEventCreateWithFlags(&evA0[i], cudaEventDisableTiming);
        cudaEventCreateWithFlags(&evG0[i], cudaEventDisableTiming);
    }
    for (int i = 0; i < 2; i++) cudaEventCreateWithFlags(&evH[i], cudaEventDisableTiming);

    const int nScanBlocks = (NN + 255) / 256;
    dim3 ggH0(HALF0 / 128, 2);
    dim3 ggH1((NN - HALF0 + 127) / 128, 2);
    dim3 ggFull((NN + 127) / 128, 2);
    auto aggBlocks = [](int nodes) { return (nodes * 32 + 255) / 256; };

    cudaEventRecord(evRoot, 0);
    cudaStreamWaitEvent(s1, evRoot, 0);
    cudaStreamWaitEvent(s2, evRoot, 0);

    // ---- s1: conversions + self-GEMM layer 0 ----
    conv_x_kernel<<<(NN * 128 + 255) / 256, 256, 0, s1>>>(x);
    cudaEventRecord(evX, s1);
    conv_w_kernel<<<(2 * 256 * 128 + 255) / 256, 256, 0, s1>>>(Wl0, Wr0, Bf0, 128);
    conv_w_kernel<<<(2 * 256 * 256 + 255) / 256, 256, 0, s1>>>(Wl1, Wr1, Bf1, 256);
    conv_w_kernel<<<(2 * 256 * 256 + 255) / 256, 256, 0, s1>>>(Wl2, Wr2, Bf2, 256);
    gemm_one<128, true, false, false><<<ggFull, 256, GSMEM, s1>>>(
        Xh, BfR0, nullptr, nullptr, nullptr, nullptr, nullptr, nullptr, P, nullptr, 0, NN);
    cudaEventRecord(evP[0], s1);

    // ---- main: CSR build ----
    zero_counts_kernel<<<(NN + 255) / 256, 256>>>();
    hist_kernel<<<(E + 255) / 256, 256>>>(dst, E);
    block_sums_kernel<<<nScanBlocks, 256>>>();
    scan_bsums_kernel<<<1, 256>>>(nScanBlocks);
    scan_final_kernel<<<nScanBlocks, 256>>>();
    scatter_kernel<<<(E + 255) / 256, 256>>>(src, dst, E);

    // =========== layer 0 ===========
    cudaStreamWaitEvent(0, evX, 0);
    agg_f16<false><<<aggBlocks(HALF0), 256>>>(Xh, Mh, 0, HALF0);
    cudaEventRecord(evA0[0], 0);
    agg_f16<false><<<aggBlocks(NN - HALF0), 256>>>(Xh, Mh, HALF0, NN);

    cudaStreamWaitEvent(s2, evA0[0], 0);
    cudaStreamWaitEvent(s2, evP[0], 0);
    gemm_one<128, false, true, true><<<ggH0, 256, GSMEM, s2>>>(
        Mh, BfL0, P, bl0, g0, b0, rm0, rv0, nullptr, h1h, 0, NN);
    cudaEventRecord(evG0[0], s2);

    cudaStreamWaitEvent(0, evP[0], 0);
    gemm_one<128, false, true, true><<<ggH1, 256, GSMEM>>>(
        Mh, BfL0, P, bl0, g0, b0, rm0, rv0, nullptr, h1h, HALF0, NN);
    cudaStreamWaitEvent(0, evG0[0], 0);
    cudaEventRecord(evH[0], 0);

    // s1: self-GEMM layer 1
    cudaStreamWaitEvent(s1, evH[0], 0);
    gemm_one<256, true, false, false><<<ggFull, 256, GSMEM, s1>>>(
        h1h, BfR1, nullptr, nullptr, nullptr, nullptr, nullptr, nullptr, P, nullptr, 0, NN);
    cudaEventRecord(evP[1], s1);

    // =========== layer 1 ===========
    agg_f16<true><<<aggBlocks(HALF0), 256>>>(h1h, Mh, 0, HALF0);
    cudaEventRecord(evA0[1], 0);
    agg_f16<true><<<aggBlocks(NN - HALF0), 256>>>(h1h, Mh, HALF0, NN);

    cudaStreamWaitEvent(s2, evA0[1], 0);
    cudaStreamWaitEvent(s2, evP[1], 0);
    gemm_one<256, false, true, true><<<ggH0, 256, GSMEM, s2>>>(
        Mh, BfL1, P, bl1, g1, b1, rm1, rv1, nullptr, h2h, 0, NN);
    cudaEventRecord(evG0[1], s2);

    cudaStreamWaitEvent(0, evP[1], 0);
    gemm_one<256, false, true, true><<<ggH1, 256, GSMEM>>>(
        Mh, BfL1, P, bl1, g1, b1, rm1, rv1, nullptr, h2h, HALF0, NN);
    cudaStreamWaitEvent(0, evG0[1], 0);
    cudaEventRecord(evH[1], 0);

    // s1: self-GEMM layer 2
    cudaStreamWaitEvent(s1, evH[1], 0);
    gemm_one<256, true, false, false><<<ggFull, 256, GSMEM, s1>>>(
        h2h, BfR2, nullptr, nullptr, nullptr, nullptr, nullptr, nullptr, P, nullptr, 0, NN);
    cudaEventRecord(evP[2], s1);

    // =========== layer 2 ===========
    agg_f16<true><<<aggBlocks(HALF0), 256>>>(h2h, Mh, 0, HALF0);
    cudaEventRecord(evA0[2], 0);
    agg_f16<true><<<aggBlocks(NN - HALF0), 256>>>(h2h, Mh, HALF0, NN);

    cudaStreamWaitEvent(s2, evA0[2], 0);
    cudaStreamWaitEvent(s2, evP[2], 0);
    gemm_one<256, false, false, false><<<ggH0, 256, GSMEM, s2>>>(
        Mh, BfL2, P, bl2, g2, b2, rm2, rv2, d_out, nullptr, 0, NN);
    cudaEventRecord(evG0[2], s2);

    cudaStreamWaitEvent(0, evP[2], 0);
    gemm_one<256, false, false, false><<<ggH1, 256, GSMEM>>>(
        Mh, BfL2, P, bl2, g2, b2, rm2, rv2, d_out, nullptr, HALF0, NN);
    cudaStreamWaitEvent(0, evG0[2], 0);

    cudaEventDestroy(evRoot);
    cudaEventDestroy(evX);
    for (int i = 0; i < 3; i++) {
        cudaEventDestroy(evP[i]);
        cudaEventDestroy(evA0[i]);
        cudaEventDestroy(evG0[i]);
    }
    for (int i = 0; i < 2; i++) cudaEventDestroy(evH[i]);
    cudaStreamDestroy(s1);
    cudaStreamDestroy(s2);
}

// round 12
// speedup vs baseline: 1.8829x; 1.1113x over previous
#include <cuda_runtime.h>
#include <cuda_fp16.h>
#include <cstdint>

#define NN 50000
#define EMAX 800000
#define EPS 1e-5f
#define HALF0 25088   // 196 * 128

__device__ __forceinline__ void cpasync16(uint32_t dst, const void* src) {
    asm volatile("cp.async.cg.shared.global [%0], [%1], 16;" :: "r"(dst), "l"(src));
}
__device__ __forceinline__ void cpasync16z(uint32_t dst, const void* src, int size) {
    asm volatile("cp.async.cg.shared.global [%0], [%1], 16, %2;" :: "r"(dst), "l"(src), "r"(size));
}
__device__ __forceinline__ void cpcommit() { asm volatile("cp.async.commit_group;" ::: "memory"); }
__device__ __forceinline__ void cpwait0() { asm volatile("cp.async.wait_group 0;" ::: "memory"); }
__device__ __forceinline__ void cpwait1() { asm volatile("cp.async.wait_group 1;" ::: "memory"); }
__device__ __forceinline__ void cpwait2() { asm volatile("cp.async.wait_group 2;" ::: "memory"); }

// ======================= scratch =======================
__device__ __half g_Xh[NN * 128];
__device__ __half g_h1h[NN * 256];
__device__ __half g_h2h[NN * 256];
__device__ __half g_Mh[NN * 256];
// concat weights: layer0 [256 n][256 k], layers1/2 [256 n][512 k]; k = [Wl rows | Wr rows]
__device__ __align__(16) __half g_Bf[256 * 256 + 2 * 256 * 512];
__device__ int g_counts[NN];
__device__ int g_offsets[NN + 1];
__device__ int g_cursor[NN];
__device__ int g_esrc[EMAX];
__device__ int g_bsum[256];
__device__ int g_boff[256];

// ======================= CSR build =======================
__global__ void zero_counts_kernel() {
    int i = blockIdx.x * blockDim.x + threadIdx.x;
    if (i < NN) g_counts[i] = 0;
}
__global__ void hist_kernel(const int* __restrict__ dst, int E) {
    int e = blockIdx.x * blockDim.x + threadIdx.x;
    if (e < E) atomicAdd(&g_counts[dst[e]], 1);
}
__global__ void block_sums_kernel() {
    __shared__ int s[256];
    int i = blockIdx.x * 256 + threadIdx.x;
    s[threadIdx.x] = (i < NN) ? g_counts[i] : 0;
    __syncthreads();
    #pragma unroll
    for (int off = 128; off > 0; off >>= 1) {
        if (threadIdx.x < off) s[threadIdx.x] += s[threadIdx.x + off];
        __syncthreads();
    }
    if (threadIdx.x == 0) g_bsum[blockIdx.x] = s[0];
}
__global__ void scan_bsums_kernel(int nb) {
    __shared__ int s[256];
    int v = (threadIdx.x < nb) ? g_bsum[threadIdx.x] : 0;
    s[threadIdx.x] = v;
    __syncthreads();
    #pragma unroll
    for (int off = 1; off < 256; off <<= 1) {
        int t = (threadIdx.x >= off) ? s[threadIdx.x - off] : 0;
        __syncthreads();
        s[threadIdx.x] += t;
        __syncthreads();
    }
    if (threadIdx.x < nb) g_boff[threadIdx.x] = s[threadIdx.x] - v;
    if (threadIdx.x == 255) g_offsets[NN] = s[255];
}
__global__ void scan_final_kernel() {
    __shared__ int s[256];
    int i = blockIdx.x * 256 + threadIdx.x;
    int v = (i < NN) ? g_counts[i] : 0;
    s[threadIdx.x] = v;
    __syncthreads();
    #pragma unroll
    for (int off = 1; off < 256; off <<= 1) {
        int t = (threadIdx.x >= off) ? s[threadIdx.x - off] : 0;
        __syncthreads();
        s[threadIdx.x] += t;
        __syncthreads();
    }
    if (i < NN) {
        g_offsets[i] = g_boff[blockIdx.x] + s[threadIdx.x] - v;
        g_cursor[i] = 0;
    }
}
__global__ void scatter_kernel(const int* __restrict__ src, const int* __restrict__ dst, int E) {
    int e = blockIdx.x * blockDim.x + threadIdx.x;
    if (e < E) {
        int d = dst[e];
        int p = atomicAdd(&g_cursor[d], 1);
        g_esrc[g_offsets[d] + p] = src[e];
    }
}

// ======================= conversion =======================
__global__ void conv_x_kernel(const float* __restrict__ x) {
    int i = blockIdx.x * blockDim.x + threadIdx.x;
    if (i < NN * 128) g_Xh[i] = __float2half(x[i]);
}
// concat weights: Bf[n * 2K + k] = (k < K ? Wl[k][n] : Wr[k-K][n]); W stored [K,256]
__global__ void conv_w_kernel(const float* __restrict__ Wl, const float* __restrict__ Wr,
                              __half* __restrict__ Bf, int K) {
    int i = blockIdx.x * blockDim.x + threadIdx.x;
    int tot = 256 * 2 * K;
    if (i >= tot) return;
    int n = i / (2 * K);
    int k = i - n * 2 * K;
    float f = (k < K) ? Wl[k * 256 + n] : Wr[(k - K) * 256 + n];
    Bf[i] = __float2half(f);
}

// ======================= mean aggregation: one warp per node =======================
template <bool WIDE>
__global__ __launch_bounds__(256) void agg_f16(const __half* __restrict__ h,
                                               __half* __restrict__ mean,
                                               int nodeBeg, int nodeEnd) {
    int w = (blockIdx.x * blockDim.x + threadIdx.x) >> 5;
    int node = nodeBeg + w;
    if (node >= nodeEnd) return;
    int lane = threadIdx.x & 31;
    int beg = g_offsets[node], end = g_offsets[node + 1];

    if (WIDE) {
        const uint4* base = reinterpret_cast<const uint4*>(h) + lane;
        float a0 = 0.f, a1 = 0.f, a2 = 0.f, a3 = 0.f, a4 = 0.f, a5 = 0.f, a6 = 0.f, a7 = 0.f;
        int e = beg;
        for (; e + 2 <= end; e += 2) {
            int s0 = g_esrc[e];
            int s1 = g_esrc[e + 1];
            uint4 t0 = __ldg(base + (size_t)s0 * 32);
            uint4 t1 = __ldg(base + (size_t)s1 * 32);
            float2 f;
            f = __half22float2(*(const __half2*)&t0.x); a0 += f.x; a1 += f.y;
            f = __half22float2(*(const __half2*)&t0.y); a2 += f.x; a3 += f.y;
            f = __half22float2(*(const __half2*)&t0.z); a4 += f.x; a5 += f.y;
            f = __half22float2(*(const __half2*)&t0.w); a6 += f.x; a7 += f.y;
            f = __half22float2(*(const __half2*)&t1.x); a0 += f.x; a1 += f.y;
            f = __half22float2(*(const __half2*)&t1.y); a2 += f.x; a3 += f.y;
            f = __half22float2(*(const __half2*)&t1.z); a4 += f.x; a5 += f.y;
            f = __half22float2(*(const __half2*)&t1.w); a6 += f.x; a7 += f.y;
        }
        for (; e < end; e++) {
            int s = g_esrc[e];
            uint4 t = __ldg(base + (size_t)s * 32);
            float2 f;
            f = __half22float2(*(const __half2*)&t.x); a0 += f.x; a1 += f.y;
            f = __half22float2(*(const __half2*)&t.y); a2 += f.x; a3 += f.y;
            f = __half22float2(*(const __half2*)&t.z); a4 += f.x; a5 += f.y;
            f = __half22float2(*(const __half2*)&t.w); a6 += f.x; a7 += f.y;
        }
        int deg = end - beg;
        float inv = 1.0f / (float)(deg > 1 ? deg : 1);
        __half2 p0 = __floats2half2_rn(a0 * inv, a1 * inv);
        __half2 p1 = __floats2half2_rn(a2 * inv, a3 * inv);
        __half2 p2 = __floats2half2_rn(a4 * inv, a5 * inv);
        __half2 p3 = __floats2half2_rn(a6 * inv, a7 * inv);
        uint4 o;
        o.x = *(uint32_t*)&p0; o.y = *(uint32_t*)&p1;
        o.z = *(uint32_t*)&p2; o.w = *(uint32_t*)&p3;
        reinterpret_cast<uint4*>(mean)[(size_t)node * 32 + lane] = o;
    } else {
        const uint2* base = reinterpret_cast<const uint2*>(h) + lane;
        float a0 = 0.f, a1 = 0.f, a2 = 0.f, a3 = 0.f;
        int e = beg;
        for (; e + 2 <= end; e += 2) {
            int s0 = g_esrc[e];
            int s1 = g_esrc[e + 1];
            uint2 t0 = __ldg(base + (size_t)s0 * 32);
            uint2 t1 = __ldg(base + (size_t)s1 * 32);
            float2 f;
            f = __half22float2(*(const __half2*)&t0.x); a0 += f.x; a1 += f.y;
            f = __half22float2(*(const __half2*)&t0.y); a2 += f.x; a3 += f.y;
            f = __half22float2(*(const __half2*)&t1.x); a0 += f.x; a1 += f.y;
            f = __half22float2(*(const __half2*)&t1.y); a2 += f.x; a3 += f.y;
        }
        for (; e < end; e++) {
            int s = g_esrc[e];
            uint2 t = __ldg(base + (size_t)s * 32);
            float2 f;
            f = __half22float2(*(const __half2*)&t.x); a0 += f.x; a1 += f.y;
            f = __half22float2(*(const __half2*)&t.y); a2 += f.x; a3 += f.y;
        }
        int deg = end - beg;
        float inv = 1.0f / (float)(deg > 1 ? deg : 1);
        __half2 p0 = __floats2half2_rn(a0 * inv, a1 * inv);
        __half2 p1 = __floats2half2_rn(a2 * inv, a3 * inv);
        uint2 o;
        o.x = *(uint32_t*)&p0; o.y = *(uint32_t*)&p1;
        reinterpret_cast<uint2*>(mean)[(size_t)node * 32 + lane] = o;
    }
}

// ======================= fp16 mma.sync helper =======================
__device__ __forceinline__ void mma16816(float* c, const uint32_t* a, uint32_t b0, uint32_t b1) {
    asm("mma.sync.aligned.m16n8k16.row.col.f32.f16.f16.f32 "
        "{%0,%1,%2,%3}, {%4,%5,%6,%7}, {%8,%9}, {%0,%1,%2,%3};"
        : "+f"(c[0]), "+f"(c[1]), "+f"(c[2]), "+f"(c[3])
        : "r"(a[0]), "r"(a[1]), "r"(a[2]), "r"(a[3]), "r"(b0), "r"(b1));
}

// ======================= concat dual-source 3-stage GEMM =======================
// D[m, 0:256] = BN( A1[m,:]@B[0:KH] + A2[m,:]@B[KH:2KH] + bias )
// A chunks kc < KH/32 come from A1 (mean), else A2 (prev activations).
#define SST 40
#define PLANE_B (128 * SST * 2)
#define BUF_B   (2 * PLANE_B)
#define NSTAGE  3
#define GSMEM   (NSTAGE * BUF_B)

template <int KH, bool PACK_OUT, bool RELU>
__global__ __launch_bounds__(256, 2) void gemm_cat(
    const __half* __restrict__ A1, const __half* __restrict__ A2,
    const __half* __restrict__ Bf,
    const float* __restrict__ blv, const float* __restrict__ gam,
    const float* __restrict__ bet, const float* __restrict__ rm,
    const float* __restrict__ rv,
    float* __restrict__ outf, __half* __restrict__ outh, int rowOff, int M)
{
    extern __shared__ __align__(16) char dsm[];
    constexpr int NC = 2 * KH / 32;
    constexpr int NC1 = KH / 32;

    int tid = threadIdx.x;
    int lane = tid & 31;
    int wid = tid >> 5;
    int g = lane >> 2;
    int tig = lane & 3;
    int wm = wid & 3;
    int wn = wid >> 2;
    int mBase = rowOff + blockIdx.x * 128;
    int nBase = blockIdx.y * 128;

    float acc[2][8][4];
    #pragma unroll
    for (int mt = 0; mt < 2; mt++)
        #pragma unroll
        for (int nt = 0; nt < 8; nt++)
            #pragma unroll
            for (int q = 0; q < 4; q++) acc[mt][nt][q] = 0.f;

    auto stageAB = [&](int kc, int buf) {
        char* base = dsm + buf * BUF_B;
        uint32_t dA = (uint32_t)__cvta_generic_to_shared(base);
        uint32_t dB = (uint32_t)__cvta_generic_to_shared(base + PLANE_B);
        const __half* Asrc = (kc < NC1) ? A1 : A2;
        int kOff = (kc < NC1) ? kc * 32 : (kc - NC1) * 32;
        #pragma unroll
        for (int i = 0; i < 2; i++) {
            int lin = tid + i * 256;
            int row = lin >> 2;
            int c8 = lin & 3;
            uint32_t doff = (uint32_t)(row * (SST * 2) + c8 * 16);
            int grow = mBase + row;
            int ok = (grow < M);
            int gr = ok ? grow : (M - 1);
            cpasync16z(dA + doff, Asrc + (size_t)gr * KH + kOff + c8 * 8, ok ? 16 : 0);
            cpasync16(dB + doff, Bf + (size_t)(nBase + row) * (2 * KH) + kc * 32 + c8 * 8);
        }
        cpcommit();
    };

    stageAB(0, 0);
    stageAB(1, 1);

    for (int kc = 0; kc < NC; kc++) {
        if (kc + 2 < NC) stageAB(kc + 2, (kc + 2) % NSTAGE);
        int rem = NC - 1 - kc;
        if (rem >= 2) cpwait2();
        else if (rem == 1) cpwait1();
        else cpwait0();
        __syncthreads();
        {
            char* base = dsm + (kc % NSTAGE) * BUF_B;
            const __half* sA = (const __half*)base;
            const __half* sB = (const __half*)(base + PLANE_B);
            #pragma unroll
            for (int ks = 0; ks < 2; ks++) {
                int k0 = ks * 16;
                uint32_t ah[2][4];
                #pragma unroll
                for (int mt = 0; mt < 2; mt++) {
                    int r0 = (wm * 32 + mt * 16 + g) * SST + k0 + 2 * tig;
                    ah[mt][0] = *(const uint32_t*)&sA[r0];
                    ah[mt][1] = *(const uint32_t*)&sA[r0 + 8 * SST];
                    ah[mt][2] = *(const uint32_t*)&sA[r0 + 8];
                    ah[mt][3] = *(const uint32_t*)&sA[r0 + 8 * SST + 8];
                }
                #pragma unroll
                for (int nt = 0; nt < 8; nt++) {
                    int b0 = (wn * 64 + nt * 8 + g) * SST + k0 + 2 * tig;
                    uint32_t bv0 = *(const uint32_t*)&sB[b0];
                    uint32_t bv1 = *(const uint32_t*)&sB[b0 + 8];
                    #pragma unroll
                    for (int mt = 0; mt < 2; mt++)
                        mma16816(acc[mt][nt], ah[mt], bv0, bv1);
                }
            }
        }
        __syncthreads();
    }

    #pragma unroll
    for (int nt = 0; nt < 8; nt++) {
        int c0 = nBase + wn * 64 + nt * 8 + 2 * tig;
        int c1 = c0 + 1;
        float sc0 = gam[c0] * rsqrtf(rv[c0] + EPS);
        float sh0 = (blv[c0] - rm[c0]) * sc0 + bet[c0];
        float sc1 = gam[c1] * rsqrtf(rv[c1] + EPS);
        float sh1 = (blv[c1] - rm[c1]) * sc1 + bet[c1];
        #pragma unroll
        for (int mt = 0; mt < 2; mt++) {
            int r0 = mBase + wm * 32 + mt * 16 + g;
            int r1 = r0 + 8;
            if (r0 < M) {
                float v00 = acc[mt][nt][0] * sc0 + sh0;
                float v01 = acc[mt][nt][1] * sc1 + sh1;
                if (RELU) { v00 = fmaxf(v00, 0.f); v01 = fmaxf(v01, 0.f); }
                if (PACK_OUT) {
                    __half2 hv = __floats2half2_rn(v00, v01);
                    *(__half2*)(outh + (size_t)r0 * 256 + c0) = hv;
                } else {
                    *(float2*)(outf + (size_t)r0 * 256 + c0) = make_float2(v00, v01);
                }
            }
            if (r1 < M) {
                float v10 = acc[mt][nt][2] * sc0 + sh0;
                float v11 = acc[mt][nt][3] * sc1 + sh1;
                if (RELU) { v10 = fmaxf(v10, 0.f); v11 = fmaxf(v11, 0.f); }
                if (PACK_OUT) {
                    __half2 hv = __floats2half2_rn(v10, v11);
                    *(__half2*)(outh + (size_t)r1 * 256 + c0) = hv;
                } else {
                    *(float2*)(outf + (size_t)r1 * 256 + c0) = make_float2(v10, v11);
                }
            }
        }
    }
}

// ======================= launch =======================
extern "C" void kernel_launch(void* const* d_in, const int* in_sizes, int n_in,
                              void* d_out, int out_size) {
    const float* x = (const float*)d_in[0];
    const int* ei = (const int*)d_in[1];
    int E = in_sizes[1] / 2;
    const int* src = ei;
    const int* dst = ei + E;

    const float* Wl0 = (const float*)d_in[2];
    const float* bl0 = (const float*)d_in[3];
    const float* Wr0 = (const float*)d_in[4];
    const float* g0 = (const float*)d_in[5];
    const float* b0 = (const float*)d_in[6];
    const float* rm0 = (const float*)d_in[7];
    const float* rv0 = (const float*)d_in[8];
    const float* Wl1 = (const float*)d_in[9];
    const float* bl1 = (const float*)d_in[10];
    const float* Wr1 = (const float*)d_in[11];
    const float* g1 = (const float*)d_in[12];
    const float* b1 = (const float*)d_in[13];
    const float* rm1 = (const float*)d_in[14];
    const float* rv1 = (const float*)d_in[15];
    const float* Wl2 = (const float*)d_in[16];
    const float* bl2 = (const float*)d_in[17];
    const float* Wr2 = (const float*)d_in[18];
    const float* g2 = (const float*)d_in[19];
    const float* b2 = (const float*)d_in[20];
    const float* rm2 = (const float*)d_in[21];
    const float* rv2 = (const float*)d_in[22];

    __half *Xh, *h1h, *h2h, *Mh, *Bf;
    cudaGetSymbolAddress((void**)&Xh, g_Xh);
    cudaGetSymbolAddress((void**)&h1h, g_h1h);
    cudaGetSymbolAddress((void**)&h2h, g_h2h);
    cudaGetSymbolAddress((void**)&Mh, g_Mh);
    cudaGetSymbolAddress((void**)&Bf, g_Bf);
    __half* Bf0 = Bf;                        // [256][256]
    __half* Bf1 = Bf0 + 256 * 256;           // [256][512]
    __half* Bf2 = Bf1 + 256 * 512;           // [256][512]

    cudaFuncSetAttribute(gemm_cat<128, true, true>, cudaFuncAttributeMaxDynamicSharedMemorySize, GSMEM);
    cudaFuncSetAttribute(gemm_cat<256, true, true>, cudaFuncAttributeMaxDynamicSharedMemorySize, GSMEM);
    cudaFuncSetAttribute(gemm_cat<256, false, false>, cudaFuncAttributeMaxDynamicSharedMemorySize, GSMEM);

    cudaStream_t s1, s2;
    cudaStreamCreateWithFlags(&s1, cudaStreamNonBlocking);
    cudaStreamCreateWithFlags(&s2, cudaStreamNonBlocking);

    cudaEvent_t evRoot, evX, evW, evA0[3], evG0[3];
    cudaEventCreateWithFlags(&evRoot, cudaEventDisableTiming);
    cudaEventCreateWithFlags(&evX, cudaEventDisableTiming);
    cudaEventCreateWithFlags(&evW, cudaEventDisableTiming);
    for (int i = 0; i < 3; i++) {
        cudaEventCreateWithFlags(&evA0[i], cudaEventDisableTiming);
        cudaEventCreateWithFlags(&evG0[i], cudaEventDisableTiming);
    }

    const int nScanBlocks = (NN + 255) / 256;
    dim3 ggH0(HALF0 / 128, 2);
    dim3 ggH1((NN - HALF0 + 127) / 128, 2);
    auto aggBlocks = [](int nodes) { return (nodes * 32 + 255) / 256; };

    cudaEventRecord(evRoot, 0);
    cudaStreamWaitEvent(s1, evRoot, 0);
    cudaStreamWaitEvent(s2, evRoot, 0);

    // ---- s1: conversions ----
    conv_x_kernel<<<(NN * 128 + 255) / 256, 256, 0, s1>>>(x);
    cudaEventRecord(evX, s1);
    conv_w_kernel<<<(256 * 256 + 255) / 256, 256, 0, s1>>>(Wl0, Wr0, Bf0, 128);
    conv_w_kernel<<<(256 * 512 + 255) / 256, 256, 0, s1>>>(Wl1, Wr1, Bf1, 256);
    conv_w_kernel<<<(256 * 512 + 255) / 256, 256, 0, s1>>>(Wl2, Wr2, Bf2, 256);
    cudaEventRecord(evW, s1);

    // ---- main: CSR build ----
    zero_counts_kernel<<<(NN + 255) / 256, 256>>>();
    hist_kernel<<<(E + 255) / 256, 256>>>(dst, E);
    block_sums_kernel<<<nScanBlocks, 256>>>();
    scan_bsums_kernel<<<1, 256>>>(nScanBlocks);
    scan_final_kernel<<<nScanBlocks, 256>>>();
    scatter_kernel<<<(E + 255) / 256, 256>>>(src, dst, E);

    // =========== layer 0 ===========
    cudaStreamWaitEvent(0, evX, 0);
    agg_f16<false><<<aggBlocks(HALF0), 256>>>(Xh, Mh, 0, HALF0);
    cudaEventRecord(evA0[0], 0);
    agg_f16<false><<<aggBlocks(NN - HALF0), 256>>>(Xh, Mh, HALF0, NN);

    cudaStreamWaitEvent(s2, evA0[0], 0);
    cudaStreamWaitEvent(s2, evW, 0);
    gemm_cat<128, true, true><<<ggH0, 256, GSMEM, s2>>>(
        Mh, Xh, Bf0, bl0, g0, b0, rm0, rv0, nullptr, h1h, 0, NN);
    cudaEventRecord(evG0[0], s2);

    cudaStreamWaitEvent(0, evW, 0);
    gemm_cat<128, true, true><<<ggH1, 256, GSMEM>>>(
        Mh, Xh, Bf0, bl0, g0, b0, rm0, rv0, nullptr, h1h, HALF0, NN);
    cudaStreamWaitEvent(0, evG0[0], 0);

    // =========== layer 1 ===========
    agg_f16<true><<<aggBlocks(HALF0), 256>>>(h1h, Mh, 0, HALF0);
    cudaEventRecord(evA0[1], 0);
    agg_f16<true><<<aggBlocks(NN - HALF0), 256>>>(h1h, Mh, HALF0, NN);

    cudaStreamWaitEvent(s2, evA0[1], 0);
    gemm_cat<256, true, true><<<ggH0, 256, GSMEM, s2>>>(
        Mh, h1h, Bf1, bl1, g1, b1, rm1, rv1, nullptr, h2h, 0, NN);
    cudaEventRecord(evG0[1], s2);

    gemm_cat<256, true, true><<<ggH1, 256, GSMEM>>>(
        Mh, h1h, Bf1, bl1, g1, b1, rm1, rv1, nullptr, h2h, HALF0, NN);
    cudaStreamWaitEvent(0, evG0[1], 0);

    // =========== layer 2 ===========
    agg_f16<true><<<aggBlocks(HALF0), 256>>>(h2h, Mh, 0, HALF0);
    cudaEventRecord(evA0[2], 0);
    agg_f16<true><<<aggBlocks(NN - HALF0), 256>>>(h2h, Mh, HALF0, NN);

    cudaStreamWaitEvent(s2, evA0[2], 0);
    gemm_cat<256, false, false><<<ggH0, 256, GSMEM, s2>>>(
        Mh, h2h, Bf2, bl2, g2, b2, rm2, rv2, (float*)d_out, nullptr, 0, NN);
    cudaEventRecord(evG0[2], s2);

    gemm_cat<256, false, false><<<ggH1, 256, GSMEM>>>(
        Mh, h2h, Bf2, bl2, g2, b2, rm2, rv2, (float*)d_out, nullptr, HALF0, NN);
    cudaStreamWaitEvent(0, evG0[2], 0);

    cudaEventDestroy(evRoot);
    cudaEventDestroy(evX);
    cudaEventDestroy(evW);
    for (int i = 0; i < 3; i++) {
        cudaEventDestroy(evA0[i]);
        cudaEventDestroy(evG0[i]);
    }
    cudaStreamDestroy(s1);
    cudaStreamDestroy(s2);
}

// round 13
// speedup vs baseline: 1.8930x; 1.0054x over previous
#include <cuda_runtime.h>
#include <cuda_fp16.h>
#include <cstdint>

#define NN 50000
#define EMAX 800000
#define EPS 1e-5f
#define HALF0 25088   // 196 * 128
#define NSCAN 196     // ceil(NN/256)

__device__ __forceinline__ void cpasync16(uint32_t dst, const void* src) {
    asm volatile("cp.async.cg.shared.global [%0], [%1], 16;" :: "r"(dst), "l"(src));
}
__device__ __forceinline__ void cpasync16z(uint32_t dst, const void* src, int size) {
    asm volatile("cp.async.cg.shared.global [%0], [%1], 16, %2;" :: "r"(dst), "l"(src), "r"(size));
}
__device__ __forceinline__ void cpcommit() { asm volatile("cp.async.commit_group;" ::: "memory"); }
__device__ __forceinline__ void cpwait0() { asm volatile("cp.async.wait_group 0;" ::: "memory"); }
__device__ __forceinline__ void cpwait1() { asm volatile("cp.async.wait_group 1;" ::: "memory"); }
__device__ __forceinline__ void cpwait2() { asm volatile("cp.async.wait_group 2;" ::: "memory"); }

// ======================= scratch =======================
__device__ __half g_Xh[NN * 128];
__device__ __half g_h1h[NN * 256];
__device__ __half g_h2h[NN * 256];
__device__ __half g_Mh[NN * 256];
__device__ __align__(16) __half g_Bf[256 * 256 + 2 * 256 * 512];
__device__ int g_counts[NN];
__device__ int g_offsets[NN + 1];
__device__ int g_cursor[NN];
__device__ int g_esrc[EMAX];
__device__ int g_bsum[NSCAN];
__device__ int g_flag[NSCAN];

// ======================= CSR build =======================
__global__ void zero_counts_kernel() {
    int i = blockIdx.x * blockDim.x + threadIdx.x;
    if (i < NN) g_counts[i] = 0;
    if (i < NSCAN) g_flag[i] = 0;
}
// hist: 4 edges per thread via int4
__global__ void hist_kernel(const int* __restrict__ dst, int E) {
    int q = blockIdx.x * blockDim.x + threadIdx.x;
    int e = q * 4;
    if (e + 4 <= E) {
        int4 d = *(const int4*)(dst + e);
        atomicAdd(&g_counts[d.x], 1);
        atomicAdd(&g_counts[d.y], 1);
        atomicAdd(&g_counts[d.z], 1);
        atomicAdd(&g_counts[d.w], 1);
    } else {
        for (int k = e; k < E; k++) atomicAdd(&g_counts[dst[k]], 1);
    }
}
// fused scan: all NSCAN blocks co-resident; publish block aggregate, sum predecessors
__global__ void scan_fused_kernel() {
    __shared__ int s[256];
    __shared__ int sp[256];
    int tid = threadIdx.x;
    int i = blockIdx.x * 256 + tid;
    int v = (i < NN) ? g_counts[i] : 0;
    s[tid] = v;
    __syncthreads();
    #pragma unroll
    for (int off = 1; off < 256; off <<= 1) {
        int t = (tid >= off) ? s[tid - off] : 0;
        __syncthreads();
        s[tid] += t;
        __syncthreads();
    }
    if (tid == 255) {
        g_bsum[blockIdx.x] = s[255];
        __threadfence();
        atomicExch(&g_flag[blockIdx.x], 1);
    }
    // sum aggregates of predecessor blocks (parallel across threads)
    int pre = 0;
    for (int b = tid; b < blockIdx.x; b += 256) {
        while (atomicAdd(&g_flag[b], 0) == 0) { }
        pre += g_bsum[b];
    }
    sp[tid] = pre;
    __syncthreads();
    #pragma unroll
    for (int off = 128; off > 0; off >>= 1) {
        if (tid < off) sp[tid] += sp[tid + off];
        __syncthreads();
    }
    int base = sp[0];
    if (i < NN) {
        g_offsets[i] = base + s[tid] - v;
        g_cursor[i] = 0;
    }
    if (blockIdx.x == NSCAN - 1 && tid == 255) g_offsets[NN] = base + s[255];
}
// scatter: 4 edges per thread via int4
__global__ void scatter_kernel(const int* __restrict__ src, const int* __restrict__ dst, int E) {
    int q = blockIdx.x * blockDim.x + threadIdx.x;
    int e = q * 4;
    if (e + 4 <= E) {
        int4 d = *(const int4*)(dst + e);
        int4 sv = *(const int4*)(src + e);
        int p;
        p = atomicAdd(&g_cursor[d.x], 1); g_esrc[g_offsets[d.x] + p] = sv.x;
        p = atomicAdd(&g_cursor[d.y], 1); g_esrc[g_offsets[d.y] + p] = sv.y;
        p = atomicAdd(&g_cursor[d.z], 1); g_esrc[g_offsets[d.z] + p] = sv.z;
        p = atomicAdd(&g_cursor[d.w], 1); g_esrc[g_offsets[d.w] + p] = sv.w;
    } else {
        for (int k = e; k < E; k++) {
            int d = dst[k];
            int p = atomicAdd(&g_cursor[d], 1);
            g_esrc[g_offsets[d] + p] = src[k];
        }
    }
}

// ======================= conversion =======================
__global__ void conv_x_kernel(const float* __restrict__ x) {
    int i = blockIdx.x * blockDim.x + threadIdx.x;
    if (i < NN * 128) g_Xh[i] = __float2half(x[i]);
}
// all three concat weight sets in one launch
#define W0_ELEMS (256 * 256)
#define W12_ELEMS (256 * 512)
__global__ void conv_w_all_kernel(const float* __restrict__ Wl0, const float* __restrict__ Wr0,
                                  const float* __restrict__ Wl1, const float* __restrict__ Wr1,
                                  const float* __restrict__ Wl2, const float* __restrict__ Wr2,
                                  __half* __restrict__ Bf) {
    int i = blockIdx.x * blockDim.x + threadIdx.x;
    int tot = W0_ELEMS + 2 * W12_ELEMS;
    if (i >= tot) return;
    const float *Wl, *Wr;
    int r, K;
    if (i < W0_ELEMS) { Wl = Wl0; Wr = Wr0; K = 128; r = i; }
    else if (i < W0_ELEMS + W12_ELEMS) { Wl = Wl1; Wr = Wr1; K = 256; r = i - W0_ELEMS; }
    else { Wl = Wl2; Wr = Wr2; K = 256; r = i - W0_ELEMS - W12_ELEMS; }
    int n = r / (2 * K);
    int k = r - n * 2 * K;
    float f = (k < K) ? Wl[k * 256 + n] : Wr[(k - K) * 256 + n];
    g_Bf[i] = __float2half(f);
}

// ======================= mean aggregation: one warp per node =======================
template <bool WIDE>
__global__ __launch_bounds__(256) void agg_f16(const __half* __restrict__ h,
                                               __half* __restrict__ mean,
                                               int nodeBeg, int nodeEnd) {
    int w = (blockIdx.x * blockDim.x + threadIdx.x) >> 5;
    int node = nodeBeg + w;
    if (node >= nodeEnd) return;
    int lane = threadIdx.x & 31;
    int beg = g_offsets[node], end = g_offsets[node + 1];

    if (WIDE) {
        const uint4* base = reinterpret_cast<const uint4*>(h) + lane;
        float a0 = 0.f, a1 = 0.f, a2 = 0.f, a3 = 0.f, a4 = 0.f, a5 = 0.f, a6 = 0.f, a7 = 0.f;
        int e = beg;
        for (; e + 2 <= end; e += 2) {
            int s0 = g_esrc[e];
            int s1 = g_esrc[e + 1];
            uint4 t0 = __ldg(base + (size_t)s0 * 32);
            uint4 t1 = __ldg(base + (size_t)s1 * 32);
            float2 f;
            f = __half22float2(*(const __half2*)&t0.x); a0 += f.x; a1 += f.y;
            f = __half22float2(*(const __half2*)&t0.y); a2 += f.x; a3 += f.y;
            f = __half22float2(*(const __half2*)&t0.z); a4 += f.x; a5 += f.y;
            f = __half22float2(*(const __half2*)&t0.w); a6 += f.x; a7 += f.y;
            f = __half22float2(*(const __half2*)&t1.x); a0 += f.x; a1 += f.y;
            f = __half22float2(*(const __half2*)&t1.y); a2 += f.x; a3 += f.y;
            f = __half22float2(*(const __half2*)&t1.z); a4 += f.x; a5 += f.y;
            f = __half22float2(*(const __half2*)&t1.w); a6 += f.x; a7 += f.y;
        }
        for (; e < end; e++) {
            int s = g_esrc[e];
            uint4 t = __ldg(base + (size_t)s * 32);
            float2 f;
            f = __half22float2(*(const __half2*)&t.x); a0 += f.x; a1 += f.y;
            f = __half22float2(*(const __half2*)&t.y); a2 += f.x; a3 += f.y;
            f = __half22float2(*(const __half2*)&t.z); a4 += f.x; a5 += f.y;
            f = __half22float2(*(const __half2*)&t.w); a6 += f.x; a7 += f.y;
        }
        int deg = end - beg;
        float inv = 1.0f / (float)(deg > 1 ? deg : 1);
        __half2 p0 = __floats2half2_rn(a0 * inv, a1 * inv);
        __half2 p1 = __floats2half2_rn(a2 * inv, a3 * inv);
        __half2 p2 = __floats2half2_rn(a4 * inv, a5 * inv);
        __half2 p3 = __floats2half2_rn(a6 * inv, a7 * inv);
        uint4 o;
        o.x = *(uint32_t*)&p0; o.y = *(uint32_t*)&p1;
        o.z = *(uint32_t*)&p2; o.w = *(uint32_t*)&p3;
        reinterpret_cast<uint4*>(mean)[(size_t)node * 32 + lane] = o;
    } else {
        const uint2* base = reinterpret_cast<const uint2*>(h) + lane;
        float a0 = 0.f, a1 = 0.f, a2 = 0.f, a3 = 0.f;
        int e = beg;
        for (; e + 2 <= end; e += 2) {
            int s0 = g_esrc[e];
            int s1 = g_esrc[e + 1];
            uint2 t0 = __ldg(base + (size_t)s0 * 32);
            uint2 t1 = __ldg(base + (size_t)s1 * 32);
            float2 f;
            f = __half22float2(*(const __half2*)&t0.x); a0 += f.x; a1 += f.y;
            f = __half22float2(*(const __half2*)&t0.y); a2 += f.x; a3 += f.y;
            f = __half22float2(*(const __half2*)&t1.x); a0 += f.x; a1 += f.y;
            f = __half22float2(*(const __half2*)&t1.y); a2 += f.x; a3 += f.y;
        }
        for (; e < end; e++) {
            int s = g_esrc[e];
            uint2 t = __ldg(base + (size_t)s * 32);
            float2 f;
            f = __half22float2(*(const __half2*)&t.x); a0 += f.x; a1 += f.y;
            f = __half22float2(*(const __half2*)&t.y); a2 += f.x; a3 += f.y;
        }
        int deg = end - beg;
        float inv = 1.0f / (float)(deg > 1 ? deg : 1);
        __half2 p0 = __floats2half2_rn(a0 * inv, a1 * inv);
        __half2 p1 = __floats2half2_rn(a2 * inv, a3 * inv);
        uint2 o;
        o.x = *(uint32_t*)&p0; o.y = *(uint32_t*)&p1;
        reinterpret_cast<uint2*>(mean)[(size_t)node * 32 + lane] = o;
    }
}

// ======================= fp16 mma.sync helper =======================
__device__ __forceinline__ void mma16816(float* c, const uint32_t* a, uint32_t b0, uint32_t b1) {
    asm("mma.sync.aligned.m16n8k16.row.col.f32.f16.f16.f32 "
        "{%0,%1,%2,%3}, {%4,%5,%6,%7}, {%8,%9}, {%0,%1,%2,%3};"
        : "+f"(c[0]), "+f"(c[1]), "+f"(c[2]), "+f"(c[3])
        : "r"(a[0]), "r"(a[1]), "r"(a[2]), "r"(a[3]), "r"(b0), "r"(b1));
}

// ======================= concat dual-source 3-stage GEMM =======================
#define SST 40
#define PLANE_B (128 * SST * 2)
#define BUF_B   (2 * PLANE_B)
#define NSTAGE  3
#define GSMEM   (NSTAGE * BUF_B)

template <int KH, bool PACK_OUT, bool RELU>
__global__ __launch_bounds__(256, 2) void gemm_cat(
    const __half* __restrict__ A1, const __half* __restrict__ A2,
    const __half* __restrict__ Bf,
    const float* __restrict__ blv, const float* __restrict__ gam,
    const float* __restrict__ bet, const float* __restrict__ rm,
    const float* __restrict__ rv,
    float* __restrict__ outf, __half* __restrict__ outh, int rowOff, int M)
{
    extern __shared__ __align__(16) char dsm[];
    constexpr int NC = 2 * KH / 32;
    constexpr int NC1 = KH / 32;

    int tid = threadIdx.x;
    int lane = tid & 31;
    int wid = tid >> 5;
    int g = lane >> 2;
    int tig = lane & 3;
    int wm = wid & 3;
    int wn = wid >> 2;
    int mBase = rowOff + blockIdx.x * 128;
    int nBase = blockIdx.y * 128;

    float acc[2][8][4];
    #pragma unroll
    for (int mt = 0; mt < 2; mt++)
        #pragma unroll
        for (int nt = 0; nt < 8; nt++)
            #pragma unroll
            for (int q = 0; q < 4; q++) acc[mt][nt][q] = 0.f;

    auto stageAB = [&](int kc, int buf) {
        char* base = dsm + buf * BUF_B;
        uint32_t dA = (uint32_t)__cvta_generic_to_shared(base);
        uint32_t dB = (uint32_t)__cvta_generic_to_shared(base + PLANE_B);
        const __half* Asrc = (kc < NC1) ? A1 : A2;
        int kOff = (kc < NC1) ? kc * 32 : (kc - NC1) * 32;
        #pragma unroll
        for (int i = 0; i < 2; i++) {
            int lin = tid + i * 256;
            int row = lin >> 2;
            int c8 = lin & 3;
            uint32_t doff = (uint32_t)(row * (SST * 2) + c8 * 16);
            int grow = mBase + row;
            int ok = (grow < M);
            int gr = ok ? grow : (M - 1);
            cpasync16z(dA + doff, Asrc + (size_t)gr * KH + kOff + c8 * 8, ok ? 16 : 0);
            cpasync16(dB + doff, Bf + (size_t)(nBase + row) * (2 * KH) + kc * 32 + c8 * 8);
        }
        cpcommit();
    };

    stageAB(0, 0);
    stageAB(1, 1);

    for (int kc = 0; kc < NC; kc++) {
        if (kc + 2 < NC) stageAB(kc + 2, (kc + 2) % NSTAGE);
        int rem = NC - 1 - kc;
        if (rem >= 2) cpwait2();
        else if (rem == 1) cpwait1();
        else cpwait0();
        __syncthreads();
        {
            char* base = dsm + (kc % NSTAGE) * BUF_B;
            const __half* sA = (const __half*)base;
            const __half* sB = (const __half*)(base + PLANE_B);
            #pragma unroll
            for (int ks = 0; ks < 2; ks++) {
                int k0 = ks * 16;
                uint32_t ah[2][4];
                #pragma unroll
                for (int mt = 0; mt < 2; mt++) {
                    int r0 = (wm * 32 + mt * 16 + g) * SST + k0 + 2 * tig;
                    ah[mt][0] = *(const uint32_t*)&sA[r0];
                    ah[mt][1] = *(const uint32_t*)&sA[r0 + 8 * SST];
                    ah[mt][2] = *(const uint32_t*)&sA[r0 + 8];
                    ah[mt][3] = *(const uint32_t*)&sA[r0 + 8 * SST + 8];
                }
                #pragma unroll
                for (int nt = 0; nt < 8; nt++) {
                    int b0 = (wn * 64 + nt * 8 + g) * SST + k0 + 2 * tig;
                    uint32_t bv0 = *(const uint32_t*)&sB[b0];
                    uint32_t bv1 = *(const uint32_t*)&sB[b0 + 8];
                    #pragma unroll
                    for (int mt = 0; mt < 2; mt++)
                        mma16816(acc[mt][nt], ah[mt], bv0, bv1);
                }
            }
        }
        __syncthreads();
    }

    #pragma unroll
    for (int nt = 0; nt < 8; nt++) {
        int c0 = nBase + wn * 64 + nt * 8 + 2 * tig;
        int c1 = c0 + 1;
        float sc0 = gam[c0] * rsqrtf(rv[c0] + EPS);
        float sh0 = (blv[c0] - rm[c0]) * sc0 + bet[c0];
        float sc1 = gam[c1] * rsqrtf(rv[c1] + EPS);
        float sh1 = (blv[c1] - rm[c1]) * sc1 + bet[c1];
        #pragma unroll
        for (int mt = 0; mt < 2; mt++) {
            int r0 = mBase + wm * 32 + mt * 16 + g;
            int r1 = r0 + 8;
            if (r0 < M) {
                float v00 = acc[mt][nt][0] * sc0 + sh0;
                float v01 = acc[mt][nt][1] * sc1 + sh1;
                if (RELU) { v00 = fmaxf(v00, 0.f); v01 = fmaxf(v01, 0.f); }
                if (PACK_OUT) {
                    __half2 hv = __floats2half2_rn(v00, v01);
                    *(__half2*)(outh + (size_t)r0 * 256 + c0) = hv;
                } else {
                    *(float2*)(outf + (size_t)r0 * 256 + c0) = make_float2(v00, v01);
                }
            }
            if (r1 < M) {
                float v10 = acc[mt][nt][2] * sc0 + sh0;
                float v11 = acc[mt][nt][3] * sc1 + sh1;
                if (RELU) { v10 = fmaxf(v10, 0.f); v11 = fmaxf(v11, 0.f); }
                if (PACK_OUT) {
                    __half2 hv = __floats2half2_rn(v10, v11);
                    *(__half2*)(outh + (size_t)r1 * 256 + c0) = hv;
                } else {
                    *(float2*)(outf + (size_t)r1 * 256 + c0) = make_float2(v10, v11);
                }
            }
        }
    }
}

// ======================= launch =======================
extern "C" void kernel_launch(void* const* d_in, const int* in_sizes, int n_in,
                              void* d_out, int out_size) {
    const float* x = (const float*)d_in[0];
    const int* ei = (const int*)d_in[1];
    int E = in_sizes[1] / 2;
    const int* src = ei;
    const int* dst = ei + E;

    const float* Wl0 = (const float*)d_in[2];
    const float* bl0 = (const float*)d_in[3];
    const float* Wr0 = (const float*)d_in[4];
    const float* g0 = (const float*)d_in[5];
    const float* b0 = (const float*)d_in[6];
    const float* rm0 = (const float*)d_in[7];
    const float* rv0 = (const float*)d_in[8];
    const float* Wl1 = (const float*)d_in[9];
    const float* bl1 = (const float*)d_in[10];
    const float* Wr1 = (const float*)d_in[11];
    const float* g1 = (const float*)d_in[12];
    const float* b1 = (const float*)d_in[13];
    const float* rm1 = (const float*)d_in[14];
    const float* rv1 = (const float*)d_in[15];
    const float* Wl2 = (const float*)d_in[16];
    const float* bl2 = (const float*)d_in[17];
    const float* Wr2 = (const float*)d_in[18];
    const float* g2 = (const float*)d_in[19];
    const float* b2 = (const float*)d_in[20];
    const float* rm2 = (const float*)d_in[21];
    const float* rv2 = (const float*)d_in[22];

    __half *Xh, *h1h, *h2h, *Mh, *Bf;
    cudaGetSymbolAddress((void**)&Xh, g_Xh);
    cudaGetSymbolAddress((void**)&h1h, g_h1h);
    cudaGetSymbolAddress((void**)&h2h, g_h2h);
    cudaGetSymbolAddress((void**)&Mh, g_Mh);
    cudaGetSymbolAddress((void**)&Bf, g_Bf);
    __half* Bf0 = Bf;
    __half* Bf1 = Bf0 + 256 * 256;
    __half* Bf2 = Bf1 + 256 * 512;

    cudaFuncSetAttribute(gemm_cat<128, true, true>, cudaFuncAttributeMaxDynamicSharedMemorySize, GSMEM);
    cudaFuncSetAttribute(gemm_cat<256, true, true>, cudaFuncAttributeMaxDynamicSharedMemorySize, GSMEM);
    cudaFuncSetAttribute(gemm_cat<256, false, false>, cudaFuncAttributeMaxDynamicSharedMemorySize, GSMEM);

    cudaStream_t s1, s2;
    cudaStreamCreateWithFlags(&s1, cudaStreamNonBlocking);
    cudaStreamCreateWithFlags(&s2, cudaStreamNonBlocking);

    cudaEvent_t evRoot, evX, evW, evA0[3], evG0[3];
    cudaEventCreateWithFlags(&evRoot, cudaEventDisableTiming);
    cudaEventCreateWithFlags(&evX, cudaEventDisableTiming);
    cudaEventCreateWithFlags(&evW, cudaEventDisableTiming);
    for (int i = 0; i < 3; i++) {
        cudaEventCreateWithFlags(&evA0[i], cudaEventDisableTiming);
        cudaEventCreateWithFlags(&evG0[i], cudaEventDisableTiming);
    }

    dim3 ggH0(HALF0 / 128, 2);
    dim3 ggH1((NN - HALF0 + 127) / 128, 2);
    auto aggBlocks = [](int nodes) { return (nodes * 32 + 255) / 256; };
    int nEdgeQuads = (E + 1023) / 1024;   // 4 edges/thread, 256 threads

    cudaEventRecord(evRoot, 0);
    cudaStreamWaitEvent(s1, evRoot, 0);
    cudaStreamWaitEvent(s2, evRoot, 0);

    // ---- s1: conversions ----
    conv_x_kernel<<<(NN * 128 + 255) / 256, 256, 0, s1>>>(x);
    cudaEventRecord(evX, s1);
    conv_w_all_kernel<<<(W0_ELEMS + 2 * W12_ELEMS + 255) / 256, 256, 0, s1>>>(
        Wl0, Wr0, Wl1, Wr1, Wl2, Wr2, Bf);
    cudaEventRecord(evW, s1);

    // ---- main: CSR build ----
    zero_counts_kernel<<<(NN + 255) / 256, 256>>>();
    hist_kernel<<<nEdgeQuads, 256>>>(dst, E);
    scan_fused_kernel<<<NSCAN, 256>>>();
    scatter_kernel<<<nEdgeQuads, 256>>>(src, dst, E);

    // =========== layer 0 ===========
    cudaStreamWaitEvent(0, evX, 0);
    agg_f16<false><<<aggBlocks(HALF0), 256>>>(Xh, Mh, 0, HALF0);
    cudaEventRecord(evA0[0], 0);
    agg_f16<false><<<aggBlocks(NN - HALF0), 256>>>(Xh, Mh, HALF0, NN);

    cudaStreamWaitEvent(s2, evA0[0], 0);
    cudaStreamWaitEvent(s2, evW, 0);
    gemm_cat<128, true, true><<<ggH0, 256, GSMEM, s2>>>(
        Mh, Xh, Bf0, bl0, g0, b0, rm0, rv0, nullptr, h1h, 0, NN);
    cudaEventRecord(evG0[0], s2);

    cudaStreamWaitEvent(0, evW, 0);
    gemm_cat<128, true, true><<<ggH1, 256, GSMEM>>>(
        Mh, Xh, Bf0, bl0, g0, b0, rm0, rv0, nullptr, h1h, HALF0, NN);
    cudaStreamWaitEvent(0, evG0[0], 0);

    // =========== layer 1 ===========
    agg_f16<true><<<aggBlocks(HALF0), 256>>>(h1h, Mh, 0, HALF0);
    cudaEventRecord(evA0[1], 0);
    agg_f16<true><<<aggBlocks(NN - HALF0), 256>>>(h1h, Mh, HALF0, NN);

    cudaStreamWaitEvent(s2, evA0[1], 0);
    gemm_cat<256, true, true><<<ggH0, 256, GSMEM, s2>>>(
        Mh, h1h, Bf1, bl1, g1, b1, rm1, rv1, nullptr, h2h, 0, NN);
    cudaEventRecord(evG0[1], s2);

    gemm_cat<256, true, true><<<ggH1, 256, GSMEM>>>(
        Mh, h1h, Bf1, bl1, g1, b1, rm1, rv1, nullptr, h2h, HALF0, NN);
    cudaStreamWaitEvent(0, evG0[1], 0);

    // =========== layer 2 ===========
    agg_f16<true><<<aggBlocks(HALF0), 256>>>(h2h, Mh, 0, HALF0);
    cudaEventRecord(evA0[2], 0);
    agg_f16<true><<<aggBlocks(NN - HALF0), 256>>>(h2h, Mh, HALF0, NN);

    cudaStreamWaitEvent(s2, evA0[2], 0);
    gemm_cat<256, false, false><<<ggH0, 256, GSMEM, s2>>>(
        Mh, h2h, Bf2, bl2, g2, b2, rm2, rv2, (float*)d_out, nullptr, 0, NN);
    cudaEventRecord(evG0[2], s2);

    gemm_cat<256, false, false><<<ggH1, 256, GSMEM>>>(
        Mh, h2h, Bf2, bl2, g2, b2, rm2, rv2, (float*)d_out, nullptr, HALF0, NN);
    cudaStreamWaitEvent(0, evG0[2], 0);

    cudaEventDestroy(evRoot);
    cudaEventDestroy(evX);
    cudaEventDestroy(evW);
    for (int i = 0; i < 3; i++) {
        cudaEventDestroy(evA0[i]);
        cudaEventDestroy(evG0[i]);
    }
    cudaStreamDestroy(s1);
    cudaStreamDestroy(s2);
}